// round 1
// baseline (speedup 1.0000x reference)
#include <cuda_runtime.h>
#include <math.h>

#define N_ATOMS 4096
#define NG      12
#define N_GRID  1728            // 12^3
#define N_TOT   5824            // N_ATOMS + N_GRID
#define HID     256
#define KNBR    32
#define NRBF    64
#define CUTOFF  12.0f
#define RBF_W   (CUTOFF / (float)NRBF)   // 0.1875
#define BIGD    1e9f
#define VNODE_Z 120

// ---------------- device scratch (no allocation allowed) ----------------
__device__ float g_allpos[N_TOT * 3];
__device__ float g_sq[N_TOT];
__device__ int   g_valid[N_TOT];
__device__ int   g_nbr[N_TOT * KNBR];
__device__ float g_dedge[N_TOT * KNBR];
__device__ float g_h[N_TOT * HID];

// ---------------- kernel 1: positions, |p|^2, atom validity ----------------
__global__ void k_setup(const float* __restrict__ pos,
                        const float* __restrict__ cell) {
    int i = blockIdx.x * blockDim.x + threadIdx.x;
    if (i >= N_TOT) return;
    float x, y, z;
    if (i < N_ATOMS) {
        x = pos[3 * i + 0]; y = pos[3 * i + 1]; z = pos[3 * i + 2];
        g_valid[i] = 1;
    } else {
        int g = i - N_ATOMS;
        int ix = g / (NG * NG), iy = (g / NG) % NG, iz = g % NG;
        float f0 = (float)ix / (float)NG;
        float f1 = (float)iy / (float)NG;
        float f2 = (float)iz / (float)NG;
        // grid_pos = frac @ cell   (cell row-major [3][3])
        x = f0 * cell[0] + f1 * cell[3] + f2 * cell[6];
        y = f0 * cell[1] + f1 * cell[4] + f2 * cell[7];
        z = f0 * cell[2] + f1 * cell[5] + f2 * cell[8];
        // validity filled by k_vmask
    }
    g_allpos[3 * i + 0] = x;
    g_allpos[3 * i + 1] = y;
    g_allpos[3 * i + 2] = z;
    g_sq[i] = x * x + y * y + z * z;
}

// ---------------- kernel 2: vnode repulsion mask ----------------
__global__ void __launch_bounds__(256) k_vmask() {
    int i = N_ATOMS + blockIdx.x;   // grid node
    float px = g_allpos[3 * i + 0];
    float py = g_allpos[3 * i + 1];
    float pz = g_allpos[3 * i + 2];
    float sqi = g_sq[i];
    float m = 3e38f;
    for (int j = threadIdx.x; j < N_ATOMS; j += 256) {
        float dot = px * g_allpos[3 * j + 0] + py * g_allpos[3 * j + 1] + pz * g_allpos[3 * j + 2];
        float d2 = sqi + g_sq[j] - 2.0f * dot;
        m = fminf(m, d2);
    }
    #pragma unroll
    for (int o = 16; o; o >>= 1) m = fminf(m, __shfl_xor_sync(0xffffffffu, m, o));
    __shared__ float wm[8];
    if ((threadIdx.x & 31) == 0) wm[threadIdx.x >> 5] = m;
    __syncthreads();
    if (threadIdx.x == 0) {
        float b = wm[0];
        #pragma unroll
        for (int w = 1; w < 8; w++) b = fminf(b, wm[w]);
        // min dist >= REPULSION (2.0)  <=>  min d2 >= 4.0
        g_valid[i] = (b >= 4.0f) ? 1 : 0;
    }
}

// ---------------- kernel 3: embedding lookup ----------------
__global__ void k_embed(const int* __restrict__ an,
                        const float* __restrict__ embed) {
    int i = blockIdx.x;
    int c = threadIdx.x;
    int z = (i < N_ATOMS) ? an[i] : VNODE_Z;
    float v = g_valid[i] ? embed[z * HID + c] : 0.0f;
    g_h[i * HID + c] = v;
}

// ---------------- kernel 4: top-K nearest neighbors per node ----------------
__global__ void __launch_bounds__(256) k_topk() {
    int i = blockIdx.x;
    __shared__ float dist[N_TOT];
    __shared__ unsigned long long wmin[8];
    if (!g_valid[i]) {
        if (threadIdx.x < KNBR) {
            g_nbr[i * KNBR + threadIdx.x] = 0;
            g_dedge[i * KNBR + threadIdx.x] = BIGD;
        }
        return;
    }
    float px = g_allpos[3 * i + 0];
    float py = g_allpos[3 * i + 1];
    float pz = g_allpos[3 * i + 2];
    float sqi = g_sq[i];
    for (int j = threadIdx.x; j < N_TOT; j += 256) {
        float dot = px * g_allpos[3 * j + 0] + py * g_allpos[3 * j + 1] + pz * g_allpos[3 * j + 2];
        float d2 = sqi + g_sq[j] - 2.0f * dot;
        if (j == i || !g_valid[j]) d2 = 3e38f;
        dist[j] = d2;
    }
    __syncthreads();
    for (int s = 0; s < KNBR; s++) {
        unsigned long long best = 0xFFFFFFFFFFFFFFFFull;
        for (int j = threadIdx.x; j < N_TOT; j += 256) {
            unsigned long long k =
                ((unsigned long long)__float_as_uint(dist[j]) << 32) | (unsigned)j;
            best = min(best, k);
        }
        #pragma unroll
        for (int o = 16; o; o >>= 1) {
            unsigned long long other = __shfl_xor_sync(0xffffffffu, best, o);
            best = min(best, other);
        }
        if ((threadIdx.x & 31) == 0) wmin[threadIdx.x >> 5] = best;
        __syncthreads();
        if (threadIdx.x == 0) {
            unsigned long long b = wmin[0];
            #pragma unroll
            for (int w = 1; w < 8; w++) b = min(b, wmin[w]);
            int idx = (int)(b & 0xFFFFFFFFull);
            float d2 = __uint_as_float((unsigned)(b >> 32));
            dist[idx] = 3e38f;
            g_nbr[i * KNBR + s] = idx;
            g_dedge[i * KNBR + s] = sqrtf(fmaxf(d2, 1e-12f));
        }
        __syncthreads();
    }
}

// ---------------- kernel 5: fused message-passing block ----------------
// One block per node. 8 warps; warp w owns edge rows 4w..4w+3; lane l owns
// columns {4l..4l+3} and {128+4l..128+4l+3} (two float4 slots).
__global__ void __launch_bounds__(256) k_main(const float* __restrict__ Wrbf,
                                              const float* __restrict__ W1,
                                              const float* __restrict__ b1,
                                              const float* __restrict__ W2,
                                              const float* __restrict__ b2,
                                              float* __restrict__ out) {
    int i = blockIdx.x;
    int tid = threadIdx.x;
    if (!g_valid[i]) {               // block-uniform branch
        out[(size_t)i * HID + tid] = 0.0f;
        return;
    }
    __shared__ float Xs[KNBR * HID];         // 32 KB  edge features
    __shared__ float Rs[KNBR * NRBF];        // 8 KB   rbf, reused as warp partials
    __shared__ float sred[HID];              // 1 KB   summed messages
    __shared__ float hi_s[HID];              // 1 KB
    __shared__ int   nbr_s[KNBR];
    __shared__ float de_s[KNBR];
    __shared__ int   cnt_s;

    if (tid < KNBR) {
        nbr_s[tid] = g_nbr[i * KNBR + tid];
        de_s[tid]  = g_dedge[i * KNBR + tid];
    }
    hi_s[tid] = g_h[(size_t)i * HID + tid];
    __syncthreads();

    // RBF expansion: Rs[e][r] = exp(-0.5*((d_e - c_r)/w)^2)
    for (int idx = tid; idx < KNBR * NRBF; idx += 256) {
        int e = idx >> 6, r = idx & 63;
        float cr = (float)r * (CUTOFF / 63.0f);
        float t = (de_s[e] - cr) / RBF_W;
        Rs[idx] = expf(-0.5f * t * t);
    }
    if (tid == 0) {
        int c = 0;
        for (int e = 0; e < KNBR; e++) if (de_s[e] <= CUTOFF) c++;
        cnt_s = c;
    }
    __syncthreads();

    int w = tid >> 5, l = tid & 31;

    // ---- step B: X[e][c] = h_i[c] + h_nbr[e][c] + (R @ Wrbf)[e][c] ----
    float4 a0[4], a1[4];
    #pragma unroll
    for (int rr = 0; rr < 4; rr++) {
        int r = 4 * w + rr;
        const float4* hn  = (const float4*)(g_h + (size_t)nbr_s[r] * HID);
        const float4* hi4 = (const float4*)hi_s;
        float4 u = hn[l],      v = hi4[l];
        a0[rr] = make_float4(u.x + v.x, u.y + v.y, u.z + v.z, u.w + v.w);
        u = hn[32 + l];        v = hi4[32 + l];
        a1[rr] = make_float4(u.x + v.x, u.y + v.y, u.z + v.z, u.w + v.w);
    }
    #pragma unroll 4
    for (int rho = 0; rho < NRBF; rho++) {
        const float4* wrow = (const float4*)(Wrbf + rho * HID);
        float4 w0 = wrow[l], w1v = wrow[32 + l];
        #pragma unroll
        for (int rr = 0; rr < 4; rr++) {
            float rv = Rs[(4 * w + rr) * NRBF + rho];
            a0[rr].x += rv * w0.x;  a0[rr].y += rv * w0.y;
            a0[rr].z += rv * w0.z;  a0[rr].w += rv * w0.w;
            a1[rr].x += rv * w1v.x; a1[rr].y += rv * w1v.y;
            a1[rr].z += rv * w1v.z; a1[rr].w += rv * w1v.w;
        }
    }
    #pragma unroll
    for (int rr = 0; rr < 4; rr++) {
        int r = 4 * w + rr;
        ((float4*)(Xs + r * HID))[l]      = a0[rr];
        ((float4*)(Xs + r * HID))[32 + l] = a1[rr];
    }
    __syncthreads();

    // ---- step C: Y = silu(X @ W1 + b1) ----
    float4 y0[4], y1[4];
    {
        float4 bv0 = ((const float4*)b1)[l];
        float4 bv1 = ((const float4*)b1)[32 + l];
        #pragma unroll
        for (int rr = 0; rr < 4; rr++) { y0[rr] = bv0; y1[rr] = bv1; }
    }
    #pragma unroll 4
    for (int k = 0; k < HID; k++) {
        const float4* w1row = (const float4*)(W1 + k * HID);
        float4 w0 = w1row[l], w1v = w1row[32 + l];
        #pragma unroll
        for (int rr = 0; rr < 4; rr++) {
            float xv = Xs[(4 * w + rr) * HID + k];
            y0[rr].x += xv * w0.x;  y0[rr].y += xv * w0.y;
            y0[rr].z += xv * w0.z;  y0[rr].w += xv * w0.w;
            y1[rr].x += xv * w1v.x; y1[rr].y += xv * w1v.y;
            y1[rr].z += xv * w1v.z; y1[rr].w += xv * w1v.w;
        }
    }

    // silu + masked sum over this warp's 4 rows
    float4 c0 = make_float4(0, 0, 0, 0), c1 = make_float4(0, 0, 0, 0);
    #pragma unroll
    for (int rr = 0; rr < 4; rr++) {
        int r = 4 * w + rr;
        if (de_s[r] <= CUTOFF) {
            float4 s0, s1;
            s0.x = y0[rr].x / (1.0f + expf(-y0[rr].x));
            s0.y = y0[rr].y / (1.0f + expf(-y0[rr].y));
            s0.z = y0[rr].z / (1.0f + expf(-y0[rr].z));
            s0.w = y0[rr].w / (1.0f + expf(-y0[rr].w));
            s1.x = y1[rr].x / (1.0f + expf(-y1[rr].x));
            s1.y = y1[rr].y / (1.0f + expf(-y1[rr].y));
            s1.z = y1[rr].z / (1.0f + expf(-y1[rr].z));
            s1.w = y1[rr].w / (1.0f + expf(-y1[rr].w));
            c0.x += s0.x; c0.y += s0.y; c0.z += s0.z; c0.w += s0.w;
            c1.x += s1.x; c1.y += s1.y; c1.z += s1.z; c1.w += s1.w;
        }
    }
    __syncthreads();   // Rs free for reuse as [8][256] warp partials
    {
        float* part = Rs;
        ((float4*)(part + w * HID))[l]      = c0;
        ((float4*)(part + w * HID))[32 + l] = c1;
    }
    __syncthreads();
    {
        float s = 0.0f;
        #pragma unroll
        for (int ww = 0; ww < 8; ww++) s += Rs[ww * HID + tid];
        sred[tid] = s;
    }
    __syncthreads();

    // ---- step D: feat = h_i + s @ W2 + cnt * b2 ----
    float f = hi_s[tid] + (float)cnt_s * b2[tid];
    #pragma unroll 8
    for (int k = 0; k < HID; k++) {
        f += sred[k] * W2[k * HID + tid];
    }
    out[(size_t)i * HID + tid] = f;
}

// ---------------- kernel 6: boolean mask outputs (as 0/1 floats) ----------------
__global__ void k_masks(float* __restrict__ out, int out_size) {
    int i = blockIdx.x * blockDim.x + threadIdx.x;
    if (i >= N_TOT) return;
    if (out_size < N_TOT * HID + 2 * N_TOT) return;
    float vn = (i >= N_ATOMS && g_valid[i]) ? 1.0f : 0.0f;   // vnode & valid
    float pn = (i < N_ATOMS) ? 1.0f : 0.0f;                   // real atoms
    out[N_TOT * HID + i] = vn;
    out[N_TOT * HID + N_TOT + i] = pn;
}

// ---------------- launcher ----------------
extern "C" void kernel_launch(void* const* d_in, const int* in_sizes, int n_in,
                              void* d_out, int out_size) {
    const float* pos   = (const float*)d_in[0];
    const int*   an    = (const int*)  d_in[1];
    const float* cell  = (const float*)d_in[2];
    const float* embed = (const float*)d_in[3];
    const float* Wrbf  = (const float*)d_in[4];
    const float* W1    = (const float*)d_in[5];
    const float* b1    = (const float*)d_in[6];
    const float* W2    = (const float*)d_in[7];
    const float* b2    = (const float*)d_in[8];
    float* out = (float*)d_out;

    k_setup<<<(N_TOT + 255) / 256, 256>>>(pos, cell);
    k_vmask<<<N_GRID, 256>>>();
    k_embed<<<N_TOT, 256>>>(an, embed);
    k_topk<<<N_TOT, 256>>>();
    k_main<<<N_TOT, 256>>>(Wrbf, W1, b1, W2, b2, out);
    k_masks<<<(N_TOT + 255) / 256, 256>>>(out, out_size);
}

// round 3
// speedup vs baseline: 2.1708x; 2.1708x over previous
#include <cuda_runtime.h>
#include <math.h>

#define N_ATOMS 4096
#define NG      12
#define N_GRID  1728
#define N_TOT   5824
#define HID     256
#define KNBR    32
#define NRBF    64
#define CUTOFF  12.0f
#define RBF_W   (CUTOFF / (float)NRBF)
#define BIGD    1e9f
#define VNODE_Z 120
#define NEMB    125
#define MAXC    2048

// ---------------- device scratch (device symbols: only touched from device code) ----------------
__device__ float4 g_pos4[N_TOT];           // x,y,z,|p|^2
__device__ int    g_valid[N_TOT];
__device__ int    g_z[N_TOT];
__device__ int    g_nbr[N_TOT * KNBR];
__device__ float  g_dedge[N_TOT * KNBR];
__device__ float  g_eW1[NEMB * HID];       // embed @ W1
__device__ float  g_WW[NRBF * HID];        // Wrbf @ W1
__device__ float  g_S[N_TOT * HID];        // summed silu messages
__device__ int    g_cnt[N_TOT];

// ---------------- kernel 1: positions, |p|^2, z, atom validity ----------------
__global__ void k_setup(const float* __restrict__ pos,
                        const int* __restrict__ an,
                        const float* __restrict__ cell) {
    int i = blockIdx.x * blockDim.x + threadIdx.x;
    if (i >= N_TOT) return;
    float x, y, z;
    if (i < N_ATOMS) {
        x = pos[3 * i + 0]; y = pos[3 * i + 1]; z = pos[3 * i + 2];
        g_valid[i] = 1;
        g_z[i] = an[i];
    } else {
        int g = i - N_ATOMS;
        int ix = g / (NG * NG), iy = (g / NG) % NG, iz = g % NG;
        float f0 = (float)ix / (float)NG;
        float f1 = (float)iy / (float)NG;
        float f2 = (float)iz / (float)NG;
        x = f0 * cell[0] + f1 * cell[3] + f2 * cell[6];
        y = f0 * cell[1] + f1 * cell[4] + f2 * cell[7];
        z = f0 * cell[2] + f1 * cell[5] + f2 * cell[8];
        g_z[i] = VNODE_Z;
    }
    g_pos4[i] = make_float4(x, y, z, x * x + y * y + z * z);
}

// ---------------- kernel 2: vnode repulsion mask ----------------
__global__ void __launch_bounds__(256) k_vmask() {
    int i = N_ATOMS + blockIdx.x;
    float4 p = g_pos4[i];
    float m = 3e38f;
    for (int j = threadIdx.x; j < N_ATOMS; j += 256) {
        float4 q = g_pos4[j];
        float d2 = p.w + q.w - 2.0f * (p.x * q.x + p.y * q.y + p.z * q.z);
        m = fminf(m, d2);
    }
    #pragma unroll
    for (int o = 16; o; o >>= 1) m = fminf(m, __shfl_xor_sync(0xffffffffu, m, o));
    __shared__ float wm[8];
    if ((threadIdx.x & 31) == 0) wm[threadIdx.x >> 5] = m;
    __syncthreads();
    if (threadIdx.x == 0) {
        float b = wm[0];
        #pragma unroll
        for (int w = 1; w < 8; w++) b = fminf(b, wm[w]);
        g_valid[i] = (b >= 4.0f) ? 1 : 0;   // min d >= 2.0
    }
}

// ---------------- kernel 3: candidate-filtered top-K ----------------
__global__ void __launch_bounds__(256) k_topk() {
    int i = blockIdx.x, tid = threadIdx.x;
    __shared__ unsigned long long cand[MAXC];
    __shared__ int ncand;
    __shared__ unsigned long long wred[8];
    if (!g_valid[i]) {
        if (tid < KNBR) { g_nbr[i * KNBR + tid] = 0; g_dedge[i * KNBR + tid] = BIGD; }
        return;
    }
    if (tid == 0) ncand = 0;
    __syncthreads();
    float4 p = g_pos4[i];
    int lane = tid & 31;
    for (int base = 0; base < N_TOT; base += 256) {
        int j = base + tid;
        bool keep = false;
        float d2 = 0.0f;
        if (j < N_TOT) {
            float4 q = g_pos4[j];
            d2 = p.w + q.w - 2.0f * (p.x * q.x + p.y * q.y + p.z * q.z);
            keep = (d2 <= 145.0f) && (j != i) && (g_valid[j] != 0);
        }
        unsigned m = __ballot_sync(0xffffffffu, keep);
        int cpos = 0;
        if (lane == 0) cpos = m ? atomicAdd(&ncand, __popc(m)) : 0;
        cpos = __shfl_sync(0xffffffffu, cpos, 0);
        if (keep) {
            int off = cpos + __popc(m & ((1u << lane) - 1u));
            if (off < MAXC)
                cand[off] = ((unsigned long long)__float_as_uint(fmaxf(d2, 0.0f)) << 32)
                            | (unsigned)j;
        }
    }
    __syncthreads();
    int nc = min(ncand, MAXC);
    for (int s = 0; s < KNBR; s++) {
        unsigned long long best = 0xFFFFFFFFFFFFFFFFull;
        int bpos = -1;
        for (int idx = tid; idx < nc; idx += 256) {
            unsigned long long v = cand[idx];
            if (v < best) { best = v; bpos = idx; }
        }
        unsigned long long wb = best;
        #pragma unroll
        for (int o = 16; o; o >>= 1) {
            unsigned long long other = __shfl_xor_sync(0xffffffffu, wb, o);
            wb = min(wb, other);
        }
        if (lane == 0) wred[tid >> 5] = wb;
        __syncthreads();
        unsigned long long gb = wred[0];
        #pragma unroll
        for (int w = 1; w < 8; w++) gb = min(gb, wred[w]);
        if (best == gb && bpos >= 0 && gb != 0xFFFFFFFFFFFFFFFFull)
            cand[bpos] = 0xFFFFFFFFFFFFFFFFull;   // pop (owner unique: j unique)
        if (tid == 0) {
            if (gb == 0xFFFFFFFFFFFFFFFFull) {
                g_nbr[i * KNBR + s] = 0;
                g_dedge[i * KNBR + s] = BIGD;
            } else {
                g_nbr[i * KNBR + s] = (int)(gb & 0xFFFFFFFFull);
                float d2 = __uint_as_float((unsigned)(gb >> 32));
                g_dedge[i * KNBR + s] = sqrtf(fmaxf(d2, 1e-12f));
            }
        }
        __syncthreads();
    }
}

// ---------------- kernel 4a/4b: precompute tables (write device symbols directly) ----------------
__global__ void k_pre_embed(const float* __restrict__ embed,
                            const float* __restrict__ W1) {
    int r = blockIdx.x, c = threadIdx.x;
    float acc = 0.0f;
    #pragma unroll 8
    for (int k = 0; k < HID; k++) acc += embed[r * HID + k] * W1[k * HID + c];
    g_eW1[r * HID + c] = acc;
}

__global__ void k_pre_rbf(const float* __restrict__ Wrbf,
                          const float* __restrict__ W1) {
    int r = blockIdx.x, c = threadIdx.x;
    float acc = 0.0f;
    #pragma unroll 8
    for (int k = 0; k < HID; k++) acc += Wrbf[r * HID + k] * W1[k * HID + c];
    g_WW[r * HID + c] = acc;
}

// ---------------- kernel 5: per-edge messages (factorized W1) ----------------
// One block per node. Warp w owns edges 4w..4w+3; lane l owns cols {4l..} & {128+4l..}.
__global__ void __launch_bounds__(256) k_msg(const float* __restrict__ b1) {
    int i = blockIdx.x, tid = threadIdx.x;
    if (!g_valid[i]) {
        g_S[(size_t)i * HID + tid] = 0.0f;
        if (tid == 0) g_cnt[i] = 0;
        return;
    }
    __shared__ float Rs[KNBR * NRBF];    // 8 KB rbf
    __shared__ float part[8 * HID];      // 8 KB warp partials
    __shared__ int   nbr_s[KNBR];
    __shared__ float de_s[KNBR];
    if (tid < KNBR) {
        nbr_s[tid] = g_nbr[i * KNBR + tid];
        de_s[tid]  = g_dedge[i * KNBR + tid];
    }
    __syncthreads();
    for (int idx = tid; idx < KNBR * NRBF; idx += 256) {
        int e = idx >> 6, r = idx & 63;
        float cr = (float)r * (CUTOFF / 63.0f);
        float t = (de_s[e] - cr) / RBF_W;
        Rs[idx] = expf(-0.5f * t * t);
    }
    if (tid == 0) {
        int c = 0;
        for (int e = 0; e < KNBR; e++) if (de_s[e] <= CUTOFF) c++;
        g_cnt[i] = c;
    }
    __syncthreads();

    int w = tid >> 5, l = tid & 31;
    int zi = g_z[i];
    const float4* ei  = (const float4*)(g_eW1 + zi * HID);
    const float4* b14 = (const float4*)b1;

    float4 a0[4], a1[4];
    #pragma unroll
    for (int rr = 0; rr < 4; rr++) {
        int zn = g_z[nbr_s[4 * w + rr]];
        const float4* en = (const float4*)(g_eW1 + zn * HID);
        float4 u = ei[l], v = en[l], bb = b14[l];
        a0[rr] = make_float4(u.x + v.x + bb.x, u.y + v.y + bb.y,
                             u.z + v.z + bb.z, u.w + v.w + bb.w);
        u = ei[32 + l]; v = en[32 + l]; bb = b14[32 + l];
        a1[rr] = make_float4(u.x + v.x + bb.x, u.y + v.y + bb.y,
                             u.z + v.z + bb.z, u.w + v.w + bb.w);
    }
    #pragma unroll 4
    for (int k = 0; k < NRBF; k++) {
        const float4* wr = (const float4*)(g_WW + k * HID);
        float4 w0 = wr[l], w1v = wr[32 + l];
        #pragma unroll
        for (int rr = 0; rr < 4; rr++) {
            float rv = Rs[(4 * w + rr) * NRBF + k];
            a0[rr].x += rv * w0.x;  a0[rr].y += rv * w0.y;
            a0[rr].z += rv * w0.z;  a0[rr].w += rv * w0.w;
            a1[rr].x += rv * w1v.x; a1[rr].y += rv * w1v.y;
            a1[rr].z += rv * w1v.z; a1[rr].w += rv * w1v.w;
        }
    }
    // silu + cutoff mask + per-warp edge sum
    float4 c0 = make_float4(0, 0, 0, 0), c1 = make_float4(0, 0, 0, 0);
    #pragma unroll
    for (int rr = 0; rr < 4; rr++) {
        if (de_s[4 * w + rr] <= CUTOFF) {
            c0.x += a0[rr].x / (1.0f + expf(-a0[rr].x));
            c0.y += a0[rr].y / (1.0f + expf(-a0[rr].y));
            c0.z += a0[rr].z / (1.0f + expf(-a0[rr].z));
            c0.w += a0[rr].w / (1.0f + expf(-a0[rr].w));
            c1.x += a1[rr].x / (1.0f + expf(-a1[rr].x));
            c1.y += a1[rr].y / (1.0f + expf(-a1[rr].y));
            c1.z += a1[rr].z / (1.0f + expf(-a1[rr].z));
            c1.w += a1[rr].w / (1.0f + expf(-a1[rr].w));
        }
    }
    ((float4*)(part + w * HID))[l]      = c0;
    ((float4*)(part + w * HID))[32 + l] = c1;
    __syncthreads();
    float s = 0.0f;
    #pragma unroll
    for (int ww = 0; ww < 8; ww++) s += part[ww * HID + tid];
    g_S[(size_t)i * HID + tid] = s;
}

// ---------------- kernel 6: feat = h + S @ W2 + cnt*b2 (32 nodes/block) ----------------
__global__ void __launch_bounds__(256) k_final(const float* __restrict__ embed,
                                               const float* __restrict__ W2,
                                               const float* __restrict__ b2,
                                               float* __restrict__ out) {
    int base = blockIdx.x * 32;
    int tid = threadIdx.x, w = tid >> 5, l = tid & 31;
    __shared__ float Ssm[32 * HID];   // 32 KB
    for (int idx = tid; idx < 32 * HID; idx += 256)
        Ssm[idx] = g_S[(size_t)(base + (idx >> 8)) * HID + (idx & 255)];
    __syncthreads();

    float4 y0[4], y1[4];
    #pragma unroll
    for (int rr = 0; rr < 4; rr++) {
        y0[rr] = make_float4(0, 0, 0, 0);
        y1[rr] = make_float4(0, 0, 0, 0);
    }
    #pragma unroll 4
    for (int k = 0; k < HID; k++) {
        const float4* w2row = (const float4*)(W2 + k * HID);
        float4 wa = w2row[l], wb = w2row[32 + l];
        #pragma unroll
        for (int rr = 0; rr < 4; rr++) {
            float sv = Ssm[(4 * w + rr) * HID + k];
            y0[rr].x += sv * wa.x; y0[rr].y += sv * wa.y;
            y0[rr].z += sv * wa.z; y0[rr].w += sv * wa.w;
            y1[rr].x += sv * wb.x; y1[rr].y += sv * wb.y;
            y1[rr].z += sv * wb.z; y1[rr].w += sv * wb.w;
        }
    }
    const float4* b24 = (const float4*)b2;
    float4 ba = b24[l], bb = b24[32 + l];
    #pragma unroll
    for (int rr = 0; rr < 4; rr++) {
        int n = base + 4 * w + rr;
        int valid = g_valid[n];
        float cnt = (float)g_cnt[n];
        const float4* e4 = (const float4*)(embed + (size_t)g_z[n] * HID);
        float4 ea = e4[l], eb = e4[32 + l];
        float4 oa, ob;
        if (valid) {
            oa = make_float4(ea.x + y0[rr].x + cnt * ba.x,
                             ea.y + y0[rr].y + cnt * ba.y,
                             ea.z + y0[rr].z + cnt * ba.z,
                             ea.w + y0[rr].w + cnt * ba.w);
            ob = make_float4(eb.x + y1[rr].x + cnt * bb.x,
                             eb.y + y1[rr].y + cnt * bb.y,
                             eb.z + y1[rr].z + cnt * bb.z,
                             eb.w + y1[rr].w + cnt * bb.w);
        } else {
            oa = make_float4(0, 0, 0, 0);
            ob = make_float4(0, 0, 0, 0);
        }
        ((float4*)(out + (size_t)n * HID))[l]      = oa;
        ((float4*)(out + (size_t)n * HID))[32 + l] = ob;
    }
}

// ---------------- kernel 7: boolean mask outputs ----------------
__global__ void k_masks(float* __restrict__ out, int out_size) {
    int i = blockIdx.x * blockDim.x + threadIdx.x;
    if (i >= N_TOT) return;
    if (out_size < N_TOT * HID + 2 * N_TOT) return;
    float vn = (i >= N_ATOMS && g_valid[i]) ? 1.0f : 0.0f;
    float pn = (i < N_ATOMS) ? 1.0f : 0.0f;
    out[N_TOT * HID + i] = vn;
    out[N_TOT * HID + N_TOT + i] = pn;
}

// ---------------- launcher ----------------
extern "C" void kernel_launch(void* const* d_in, const int* in_sizes, int n_in,
                              void* d_out, int out_size) {
    const float* pos   = (const float*)d_in[0];
    const int*   an    = (const int*)  d_in[1];
    const float* cell  = (const float*)d_in[2];
    const float* embed = (const float*)d_in[3];
    const float* Wrbf  = (const float*)d_in[4];
    const float* W1    = (const float*)d_in[5];
    const float* b1    = (const float*)d_in[6];
    const float* W2    = (const float*)d_in[7];
    const float* b2    = (const float*)d_in[8];
    float* out = (float*)d_out;

    k_setup<<<(N_TOT + 255) / 256, 256>>>(pos, an, cell);
    k_vmask<<<N_GRID, 256>>>();
    k_pre_embed<<<NEMB, 256>>>(embed, W1);
    k_pre_rbf<<<NRBF, 256>>>(Wrbf, W1);
    k_topk<<<N_TOT, 256>>>();
    k_msg<<<N_TOT, 256>>>(b1);
    k_final<<<N_TOT / 32, 256>>>(embed, W2, b2, out);
    k_masks<<<(N_TOT + 255) / 256, 256>>>(out, out_size);
}

// round 4
// speedup vs baseline: 2.6722x; 1.2310x over previous
#include <cuda_runtime.h>
#include <math.h>

#define N_ATOMS 4096
#define NG      12
#define N_GRID  1728
#define N_TOT   5824
#define HID     256
#define KNBR    32
#define NRBF    64
#define CUTOFF  12.0f
#define RBF_W   (CUTOFF / (float)NRBF)
#define BIGD    1e9f
#define VNODE_Z 120
#define NEMB    125
#define MAXC    2048

// ---------------- device scratch ----------------
__device__ float4 g_pos4[N_TOT];
__device__ int    g_valid[N_TOT];
__device__ int    g_z[N_TOT];
__device__ int    g_nbr[N_TOT * KNBR];
__device__ float  g_dedge[N_TOT * KNBR];
__device__ float  g_eW1[NEMB * HID];       // embed @ W1
__device__ float  g_WW[NRBF * HID];        // Wrbf @ W1
__device__ float  g_S[N_TOT * HID];
__device__ int    g_cnt[N_TOT];

// ---------------- kernel 1: positions, |p|^2, z, atom validity ----------------
__global__ void k_setup(const float* __restrict__ pos,
                        const int* __restrict__ an,
                        const float* __restrict__ cell) {
    int i = blockIdx.x * blockDim.x + threadIdx.x;
    if (i >= N_TOT) return;
    float x, y, z;
    if (i < N_ATOMS) {
        x = pos[3 * i + 0]; y = pos[3 * i + 1]; z = pos[3 * i + 2];
        g_valid[i] = 1;
        g_z[i] = an[i];
    } else {
        int g = i - N_ATOMS;
        int ix = g / (NG * NG), iy = (g / NG) % NG, iz = g % NG;
        float f0 = (float)ix / (float)NG;
        float f1 = (float)iy / (float)NG;
        float f2 = (float)iz / (float)NG;
        x = f0 * cell[0] + f1 * cell[3] + f2 * cell[6];
        y = f0 * cell[1] + f1 * cell[4] + f2 * cell[7];
        z = f0 * cell[2] + f1 * cell[5] + f2 * cell[8];
        g_z[i] = VNODE_Z;
    }
    g_pos4[i] = make_float4(x, y, z, x * x + y * y + z * z);
}

// ---------------- kernel 2: vnode repulsion mask ----------------
__global__ void __launch_bounds__(256) k_vmask() {
    int i = N_ATOMS + blockIdx.x;
    float4 p = g_pos4[i];
    float m = 3e38f;
    for (int j = threadIdx.x; j < N_ATOMS; j += 256) {
        float4 q = g_pos4[j];
        float d2 = p.w + q.w - 2.0f * (p.x * q.x + p.y * q.y + p.z * q.z);
        m = fminf(m, d2);
    }
    #pragma unroll
    for (int o = 16; o; o >>= 1) m = fminf(m, __shfl_xor_sync(0xffffffffu, m, o));
    __shared__ float wm[8];
    if ((threadIdx.x & 31) == 0) wm[threadIdx.x >> 5] = m;
    __syncthreads();
    if (threadIdx.x == 0) {
        float b = wm[0];
        #pragma unroll
        for (int w = 1; w < 8; w++) b = fminf(b, wm[w]);
        g_valid[i] = (b >= 4.0f) ? 1 : 0;
    }
}

// ---------------- kernel 3: merged precompute: [embed;Wrbf] @ W1 ----------------
__global__ void __launch_bounds__(256) k_pre(const float* __restrict__ embed,
                                             const float* __restrict__ Wrbf,
                                             const float* __restrict__ W1) {
    int r = blockIdx.x, c = threadIdx.x;
    const float* A = (r < NEMB) ? (embed + (size_t)r * HID)
                                : (Wrbf + (size_t)(r - NEMB) * HID);
    float a0 = 0.f, a1 = 0.f, a2 = 0.f, a3 = 0.f;
    #pragma unroll 8
    for (int k = 0; k < HID; k += 4) {
        a0 += A[k + 0] * W1[(k + 0) * HID + c];
        a1 += A[k + 1] * W1[(k + 1) * HID + c];
        a2 += A[k + 2] * W1[(k + 2) * HID + c];
        a3 += A[k + 3] * W1[(k + 3) * HID + c];
    }
    float acc = (a0 + a1) + (a2 + a3);
    if (r < NEMB) g_eW1[r * HID + c] = acc;
    else          g_WW[(r - NEMB) * HID + c] = acc;
}

// ---------------- kernel 4: candidate-filtered top-K ----------------
__global__ void __launch_bounds__(256) k_topk() {
    int i = blockIdx.x, tid = threadIdx.x;
    __shared__ unsigned long long cand[MAXC];
    __shared__ int ncand;
    __shared__ unsigned long long wred[8];
    if (!g_valid[i]) {
        if (tid < KNBR) { g_nbr[i * KNBR + tid] = 0; g_dedge[i * KNBR + tid] = BIGD; }
        return;
    }
    if (tid == 0) ncand = 0;
    __syncthreads();
    float4 p = g_pos4[i];
    int lane = tid & 31;
    for (int base = 0; base < N_TOT; base += 256) {
        int j = base + tid;
        bool keep = false;
        float d2 = 0.0f;
        if (j < N_TOT) {
            float4 q = g_pos4[j];
            d2 = p.w + q.w - 2.0f * (p.x * q.x + p.y * q.y + p.z * q.z);
            keep = (d2 <= 145.0f) && (j != i) && (g_valid[j] != 0);
        }
        unsigned m = __ballot_sync(0xffffffffu, keep);
        int cpos = 0;
        if (lane == 0) cpos = m ? atomicAdd(&ncand, __popc(m)) : 0;
        cpos = __shfl_sync(0xffffffffu, cpos, 0);
        if (keep) {
            int off = cpos + __popc(m & ((1u << lane) - 1u));
            if (off < MAXC)
                cand[off] = ((unsigned long long)__float_as_uint(fmaxf(d2, 0.0f)) << 32)
                            | (unsigned)j;
        }
    }
    __syncthreads();
    int nc = min(ncand, MAXC);
    for (int s = 0; s < KNBR; s++) {
        unsigned long long best = 0xFFFFFFFFFFFFFFFFull;
        int bpos = -1;
        for (int idx = tid; idx < nc; idx += 256) {
            unsigned long long v = cand[idx];
            if (v < best) { best = v; bpos = idx; }
        }
        unsigned long long wb = best;
        #pragma unroll
        for (int o = 16; o; o >>= 1) {
            unsigned long long other = __shfl_xor_sync(0xffffffffu, wb, o);
            wb = min(wb, other);
        }
        if (lane == 0) wred[tid >> 5] = wb;
        __syncthreads();
        unsigned long long gb = wred[0];
        #pragma unroll
        for (int w = 1; w < 8; w++) gb = min(gb, wred[w]);
        if (best == gb && bpos >= 0 && gb != 0xFFFFFFFFFFFFFFFFull)
            cand[bpos] = 0xFFFFFFFFFFFFFFFFull;
        if (tid == 0) {
            if (gb == 0xFFFFFFFFFFFFFFFFull) {
                g_nbr[i * KNBR + s] = 0;
                g_dedge[i * KNBR + s] = BIGD;
            } else {
                g_nbr[i * KNBR + s] = (int)(gb & 0xFFFFFFFFull);
                float d2 = __uint_as_float((unsigned)(gb >> 32));
                g_dedge[i * KNBR + s] = sqrtf(fmaxf(d2, 1e-12f));
            }
        }
        __syncthreads();
    }
}

// ---------------- kernel 5: per-edge messages, sparse RBF ----------------
// One block per node. Warp w owns edges 4w..4w+3 (distance-sorted -> coherent
// active RBF windows); lane l owns cols {4l..4l+3} and {128+4l..128+4l+3}.
__global__ void __launch_bounds__(256) k_msg(const float* __restrict__ b1) {
    int i = blockIdx.x, tid = threadIdx.x;
    if (!g_valid[i]) {
        g_S[(size_t)i * HID + tid] = 0.0f;
        if (tid == 0) g_cnt[i] = 0;
        return;
    }
    __shared__ float Rs[KNBR * NRBF];
    __shared__ float part[8 * HID];
    __shared__ int   nbr_s[KNBR];
    __shared__ float de_s[KNBR];
    if (tid < KNBR) {
        nbr_s[tid] = g_nbr[i * KNBR + tid];
        de_s[tid]  = g_dedge[i * KNBR + tid];
    }
    __syncthreads();
    for (int idx = tid; idx < KNBR * NRBF; idx += 256) {
        int e = idx >> 6, r = idx & 63;
        float cr = (float)r * (CUTOFF / 63.0f);
        float t = (de_s[e] - cr) / RBF_W;
        float t2 = t * t;
        // beyond t^2 > 96: exp(-48) ~ 1.4e-21, negligible -> hard zero enables skip
        Rs[idx] = (t2 < 96.0f) ? expf(-0.5f * t2) : 0.0f;
    }
    if (tid == 0) {
        int c = 0;
        for (int e = 0; e < KNBR; e++) if (de_s[e] <= CUTOFF) c++;
        g_cnt[i] = c;
    }
    __syncthreads();

    int w = tid >> 5, l = tid & 31;
    int zi = g_z[i];
    const float4* ei  = (const float4*)(g_eW1 + zi * HID);
    const float4* b14 = (const float4*)b1;

    float4 a0[4], a1[4];
    #pragma unroll
    for (int rr = 0; rr < 4; rr++) {
        int zn = g_z[nbr_s[4 * w + rr]];
        const float4* en = (const float4*)(g_eW1 + zn * HID);
        float4 u = ei[l], v = en[l], bb = b14[l];
        a0[rr] = make_float4(u.x + v.x + bb.x, u.y + v.y + bb.y,
                             u.z + v.z + bb.z, u.w + v.w + bb.w);
        u = ei[32 + l]; v = en[32 + l]; bb = b14[32 + l];
        a1[rr] = make_float4(u.x + v.x + bb.x, u.y + v.y + bb.y,
                             u.z + v.z + bb.z, u.w + v.w + bb.w);
    }
    const float* rs_w = Rs + (4 * w) * NRBF;
    for (int k = 0; k < NRBF; k++) {
        float rv0 = rs_w[k];
        float rv1 = rs_w[NRBF + k];
        float rv2 = rs_w[2 * NRBF + k];
        float rv3 = rs_w[3 * NRBF + k];
        // lane-invariant values -> warp-uniform branch, real skip
        if (rv0 + rv1 + rv2 + rv3 > 0.0f) {
            const float4* wr = (const float4*)(g_WW + k * HID);
            float4 w0 = wr[l], w1v = wr[32 + l];
            a0[0].x += rv0 * w0.x;  a0[0].y += rv0 * w0.y;
            a0[0].z += rv0 * w0.z;  a0[0].w += rv0 * w0.w;
            a1[0].x += rv0 * w1v.x; a1[0].y += rv0 * w1v.y;
            a1[0].z += rv0 * w1v.z; a1[0].w += rv0 * w1v.w;
            a0[1].x += rv1 * w0.x;  a0[1].y += rv1 * w0.y;
            a0[1].z += rv1 * w0.z;  a0[1].w += rv1 * w0.w;
            a1[1].x += rv1 * w1v.x; a1[1].y += rv1 * w1v.y;
            a1[1].z += rv1 * w1v.z; a1[1].w += rv1 * w1v.w;
            a0[2].x += rv2 * w0.x;  a0[2].y += rv2 * w0.y;
            a0[2].z += rv2 * w0.z;  a0[2].w += rv2 * w0.w;
            a1[2].x += rv2 * w1v.x; a1[2].y += rv2 * w1v.y;
            a1[2].z += rv2 * w1v.z; a1[2].w += rv2 * w1v.w;
            a0[3].x += rv3 * w0.x;  a0[3].y += rv3 * w0.y;
            a0[3].z += rv3 * w0.z;  a0[3].w += rv3 * w0.w;
            a1[3].x += rv3 * w1v.x; a1[3].y += rv3 * w1v.y;
            a1[3].z += rv3 * w1v.z; a1[3].w += rv3 * w1v.w;
        }
    }
    float4 c0 = make_float4(0, 0, 0, 0), c1 = make_float4(0, 0, 0, 0);
    #pragma unroll
    for (int rr = 0; rr < 4; rr++) {
        if (de_s[4 * w + rr] <= CUTOFF) {
            c0.x += a0[rr].x / (1.0f + expf(-a0[rr].x));
            c0.y += a0[rr].y / (1.0f + expf(-a0[rr].y));
            c0.z += a0[rr].z / (1.0f + expf(-a0[rr].z));
            c0.w += a0[rr].w / (1.0f + expf(-a0[rr].w));
            c1.x += a1[rr].x / (1.0f + expf(-a1[rr].x));
            c1.y += a1[rr].y / (1.0f + expf(-a1[rr].y));
            c1.z += a1[rr].z / (1.0f + expf(-a1[rr].z));
            c1.w += a1[rr].w / (1.0f + expf(-a1[rr].w));
        }
    }
    ((float4*)(part + w * HID))[l]      = c0;
    ((float4*)(part + w * HID))[32 + l] = c1;
    __syncthreads();
    float s = 0.0f;
    #pragma unroll
    for (int ww = 0; ww < 8; ww++) s += part[ww * HID + tid];
    g_S[(size_t)i * HID + tid] = s;
}

// ---------------- kernel 6: feat = h + S@W2 + cnt*b2, plus masks ----------------
__global__ void __launch_bounds__(256) k_final(const float* __restrict__ embed,
                                               const float* __restrict__ W2,
                                               const float* __restrict__ b2,
                                               float* __restrict__ out,
                                               int out_size) {
    int base = blockIdx.x * 32;
    int tid = threadIdx.x, w = tid >> 5, l = tid & 31;
    __shared__ float Ssm[32 * HID];
    for (int idx = tid; idx < 32 * HID; idx += 256)
        Ssm[idx] = g_S[(size_t)(base + (idx >> 8)) * HID + (idx & 255)];
    __syncthreads();

    float4 y0[4], y1[4];
    #pragma unroll
    for (int rr = 0; rr < 4; rr++) {
        y0[rr] = make_float4(0, 0, 0, 0);
        y1[rr] = make_float4(0, 0, 0, 0);
    }
    #pragma unroll 4
    for (int k = 0; k < HID; k++) {
        const float4* w2row = (const float4*)(W2 + k * HID);
        float4 wa = w2row[l], wb = w2row[32 + l];
        #pragma unroll
        for (int rr = 0; rr < 4; rr++) {
            float sv = Ssm[(4 * w + rr) * HID + k];
            y0[rr].x += sv * wa.x; y0[rr].y += sv * wa.y;
            y0[rr].z += sv * wa.z; y0[rr].w += sv * wa.w;
            y1[rr].x += sv * wb.x; y1[rr].y += sv * wb.y;
            y1[rr].z += sv * wb.z; y1[rr].w += sv * wb.w;
        }
    }
    const float4* b24 = (const float4*)b2;
    float4 ba = b24[l], bb = b24[32 + l];
    #pragma unroll
    for (int rr = 0; rr < 4; rr++) {
        int n = base + 4 * w + rr;
        int valid = g_valid[n];
        float cnt = (float)g_cnt[n];
        const float4* e4 = (const float4*)(embed + (size_t)g_z[n] * HID);
        float4 ea = e4[l], eb = e4[32 + l];
        float4 oa = make_float4(0, 0, 0, 0), ob = make_float4(0, 0, 0, 0);
        if (valid) {
            oa = make_float4(ea.x + y0[rr].x + cnt * ba.x,
                             ea.y + y0[rr].y + cnt * ba.y,
                             ea.z + y0[rr].z + cnt * ba.z,
                             ea.w + y0[rr].w + cnt * ba.w);
            ob = make_float4(eb.x + y1[rr].x + cnt * bb.x,
                             eb.y + y1[rr].y + cnt * bb.y,
                             eb.z + y1[rr].z + cnt * bb.z,
                             eb.w + y1[rr].w + cnt * bb.w);
        }
        ((float4*)(out + (size_t)n * HID))[l]      = oa;
        ((float4*)(out + (size_t)n * HID))[32 + l] = ob;
    }
    // masks folded in: node base+tid for tid<32
    if (tid < 32 && out_size >= N_TOT * HID + 2 * N_TOT) {
        int n = base + tid;
        out[N_TOT * HID + n] = (n >= N_ATOMS && g_valid[n]) ? 1.0f : 0.0f;
        out[N_TOT * HID + N_TOT + n] = (n < N_ATOMS) ? 1.0f : 0.0f;
    }
}

// ---------------- launcher ----------------
extern "C" void kernel_launch(void* const* d_in, const int* in_sizes, int n_in,
                              void* d_out, int out_size) {
    const float* pos   = (const float*)d_in[0];
    const int*   an    = (const int*)  d_in[1];
    const float* cell  = (const float*)d_in[2];
    const float* embed = (const float*)d_in[3];
    const float* Wrbf  = (const float*)d_in[4];
    const float* W1    = (const float*)d_in[5];
    const float* b1    = (const float*)d_in[6];
    const float* W2    = (const float*)d_in[7];
    const float* b2    = (const float*)d_in[8];
    float* out = (float*)d_out;

    k_setup<<<(N_TOT + 255) / 256, 256>>>(pos, an, cell);
    k_vmask<<<N_GRID, 256>>>();
    k_pre<<<NEMB + NRBF, 256>>>(embed, Wrbf, W1);
    k_topk<<<N_TOT, 256>>>();
    k_msg<<<N_TOT, 256>>>(b1);
    k_final<<<N_TOT / 32, 256>>>(embed, W2, b2, out, out_size);
}

// round 5
// speedup vs baseline: 4.3984x; 1.6460x over previous
#include <cuda_runtime.h>
#include <math.h>

#define N_ATOMS 4096
#define NG      12
#define N_GRID  1728
#define N_TOT   5824
#define HID     256
#define KNBR    32
#define NRBF    64
#define CUTOFF  12.0f
#define RBF_W   (CUTOFF / (float)NRBF)
#define BIGD    1e9f
#define VNODE_Z 120
#define NEMB    125
#define MAXC    1536
#define NBIN    128
#define BINCAP  256
#define U64MAX  0xFFFFFFFFFFFFFFFFull

// ---------------- device scratch ----------------
__device__ float4 g_pos4[N_TOT];
__device__ int    g_valid[N_TOT];
__device__ int    g_z[N_TOT];
__device__ int    g_nbr[N_TOT * KNBR];
__device__ float  g_dedge[N_TOT * KNBR];
__device__ float  g_eW1[NEMB * HID];       // embed @ W1
__device__ float  g_WW[NRBF * HID];        // Wrbf @ W1
__device__ float  g_S[N_TOT * HID];
__device__ int    g_cnt[N_TOT];

// ---------------- kernel 1 ----------------
__global__ void k_setup(const float* __restrict__ pos,
                        const int* __restrict__ an,
                        const float* __restrict__ cell) {
    int i = blockIdx.x * blockDim.x + threadIdx.x;
    if (i >= N_TOT) return;
    float x, y, z;
    if (i < N_ATOMS) {
        x = pos[3 * i + 0]; y = pos[3 * i + 1]; z = pos[3 * i + 2];
        g_valid[i] = 1;
        g_z[i] = an[i];
    } else {
        int g = i - N_ATOMS;
        int ix = g / (NG * NG), iy = (g / NG) % NG, iz = g % NG;
        float f0 = (float)ix / (float)NG;
        float f1 = (float)iy / (float)NG;
        float f2 = (float)iz / (float)NG;
        x = f0 * cell[0] + f1 * cell[3] + f2 * cell[6];
        y = f0 * cell[1] + f1 * cell[4] + f2 * cell[7];
        z = f0 * cell[2] + f1 * cell[5] + f2 * cell[8];
        g_z[i] = VNODE_Z;
    }
    g_pos4[i] = make_float4(x, y, z, x * x + y * y + z * z);
}

// ---------------- kernel 2: vnode repulsion mask ----------------
__global__ void __launch_bounds__(256) k_vmask() {
    int i = N_ATOMS + blockIdx.x;
    float4 p = g_pos4[i];
    float m = 3e38f;
    for (int j = threadIdx.x; j < N_ATOMS; j += 256) {
        float4 q = g_pos4[j];
        float d2 = p.w + q.w - 2.0f * (p.x * q.x + p.y * q.y + p.z * q.z);
        m = fminf(m, d2);
    }
    #pragma unroll
    for (int o = 16; o; o >>= 1) m = fminf(m, __shfl_xor_sync(0xffffffffu, m, o));
    __shared__ float wm[8];
    if ((threadIdx.x & 31) == 0) wm[threadIdx.x >> 5] = m;
    __syncthreads();
    if (threadIdx.x == 0) {
        float b = wm[0];
        #pragma unroll
        for (int w = 1; w < 8; w++) b = fminf(b, wm[w]);
        g_valid[i] = (b >= 4.0f) ? 1 : 0;
    }
}

// ---------------- kernel 3: merged precompute ----------------
__global__ void __launch_bounds__(256) k_pre(const float* __restrict__ embed,
                                             const float* __restrict__ Wrbf,
                                             const float* __restrict__ W1) {
    int r = blockIdx.x, c = threadIdx.x;
    const float* A = (r < NEMB) ? (embed + (size_t)r * HID)
                                : (Wrbf + (size_t)(r - NEMB) * HID);
    float a0 = 0.f, a1 = 0.f, a2 = 0.f, a3 = 0.f;
    #pragma unroll 8
    for (int k = 0; k < HID; k += 4) {
        a0 += A[k + 0] * W1[(k + 0) * HID + c];
        a1 += A[k + 1] * W1[(k + 1) * HID + c];
        a2 += A[k + 2] * W1[(k + 2) * HID + c];
        a3 += A[k + 3] * W1[(k + 3) * HID + c];
    }
    float acc = (a0 + a1) + (a2 + a3);
    if (r < NEMB) g_eW1[r * HID + c] = acc;
    else          g_WW[(r - NEMB) * HID + c] = acc;
}

// ---------------- kernel 4: histogram-select top-K ----------------
__global__ void __launch_bounds__(256) k_topk() {
    int i = blockIdx.x, tid = threadIdx.x;
    __shared__ unsigned long long cand[MAXC];
    __shared__ unsigned long long binbuf[BINCAP];
    __shared__ unsigned long long sel[KNBR];
    __shared__ int hist[NBIN];
    __shared__ int ncand, nsel, nbin, s_B;
    if (!g_valid[i]) {
        if (tid < KNBR) { g_nbr[i * KNBR + tid] = 0; g_dedge[i * KNBR + tid] = BIGD; }
        return;
    }
    if (tid == 0) { ncand = 0; nsel = 0; nbin = 0; }
    if (tid < NBIN) hist[tid] = 0;
    __syncthreads();

    // --- phase A: distance sweep + candidate compaction (d2 <= 145) ---
    float4 p = g_pos4[i];
    int lane = tid & 31;
    for (int base = 0; base < N_TOT; base += 256) {
        int j = base + tid;
        bool keep = false;
        float d2 = 0.0f;
        if (j < N_TOT) {
            float4 q = g_pos4[j];
            d2 = p.w + q.w - 2.0f * (p.x * q.x + p.y * q.y + p.z * q.z);
            keep = (d2 <= 145.0f) && (j != i) && (g_valid[j] != 0);
        }
        unsigned m = __ballot_sync(0xffffffffu, keep);
        int cpos = 0;
        if (lane == 0) cpos = m ? atomicAdd(&ncand, __popc(m)) : 0;
        cpos = __shfl_sync(0xffffffffu, cpos, 0);
        if (keep) {
            int off = cpos + __popc(m & ((1u << lane) - 1u));
            if (off < MAXC)
                cand[off] = ((unsigned long long)__float_as_uint(fmaxf(d2, 0.0f)) << 32)
                            | (unsigned)j;
        }
    }
    __syncthreads();
    int nc = min(ncand, MAXC);

    if (nc <= KNBR) {
        // select all, pad with U64MAX
        if (tid < KNBR) sel[tid] = (tid < nc) ? cand[tid] : U64MAX;
        __syncthreads();
    } else {
        // --- phase B: histogram over d2 in [0,145], 128 bins ---
        for (int idx = tid; idx < nc; idx += 256) {
            float d2 = __uint_as_float((unsigned)(cand[idx] >> 32));
            int b = min(NBIN - 1, (int)(d2 * ((float)NBIN / 145.0f)));
            atomicAdd(&hist[b], 1);
        }
        __syncthreads();
        if (tid == 0) {
            int c = 0, B = NBIN - 1;
            for (int b = 0; b < NBIN; b++) {
                if (c + hist[b] >= KNBR) { B = b; break; }
                c += hist[b];
            }
            s_B = B;
        }
        __syncthreads();
        int B = s_B;
        // --- phase C: collect below-threshold + threshold-bin candidates ---
        for (int idx = tid; idx < nc; idx += 256) {
            unsigned long long key = cand[idx];
            float d2 = __uint_as_float((unsigned)(key >> 32));
            int b = min(NBIN - 1, (int)(d2 * ((float)NBIN / 145.0f)));
            if (b < B) {
                sel[atomicAdd(&nsel, 1)] = key;
            } else if (b == B) {
                int pp = atomicAdd(&nbin, 1);
                if (pp < BINCAP) binbuf[pp] = key;
            }
        }
        __syncthreads();
        if (tid == 0) {
            int have = nsel;                 // == count of bins < B  (< KNBR)
            int m = KNBR - have;
            int bc = min(nbin, BINCAP);
            for (int s = 0; s < m; s++) {
                unsigned long long best = U64MAX;
                int bi = -1;
                for (int t = 0; t < bc; t++)
                    if (binbuf[t] < best) { best = binbuf[t]; bi = t; }
                if (bi >= 0) binbuf[bi] = U64MAX;
                sel[have + s] = best;
            }
        }
        __syncthreads();
    }

    // --- phase D: warp-0 bitonic sort of 32 keys (ascending) + write out ---
    if (tid < 32) {
        unsigned long long v = sel[tid];
        #pragma unroll
        for (int k = 2; k <= 32; k <<= 1) {
            #pragma unroll
            for (int j = k >> 1; j > 0; j >>= 1) {
                unsigned long long o = __shfl_xor_sync(0xffffffffu, v, j);
                bool up = ((tid & k) == 0);
                bool lower = ((tid & j) == 0);
                unsigned long long mn = min(v, o), mx = max(v, o);
                v = (up == lower) ? mn : mx;
            }
        }
        if (v == U64MAX) {
            g_nbr[i * KNBR + tid] = 0;
            g_dedge[i * KNBR + tid] = BIGD;
        } else {
            g_nbr[i * KNBR + tid] = (int)(v & 0xFFFFFFFFull);
            float d2 = __uint_as_float((unsigned)(v >> 32));
            g_dedge[i * KNBR + tid] = sqrtf(fmaxf(d2, 1e-12f));
        }
    }
}

// ---------------- kernel 5: per-edge messages, sparse RBF ----------------
__global__ void __launch_bounds__(256) k_msg(const float* __restrict__ b1) {
    int i = blockIdx.x, tid = threadIdx.x;
    if (!g_valid[i]) {
        g_S[(size_t)i * HID + tid] = 0.0f;
        if (tid == 0) g_cnt[i] = 0;
        return;
    }
    __shared__ float Rs[KNBR * NRBF];
    __shared__ float part[8 * HID];
    __shared__ int   nbr_s[KNBR];
    __shared__ float de_s[KNBR];
    if (tid < KNBR) {
        nbr_s[tid] = g_nbr[i * KNBR + tid];
        de_s[tid]  = g_dedge[i * KNBR + tid];
    }
    __syncthreads();
    for (int idx = tid; idx < KNBR * NRBF; idx += 256) {
        int e = idx >> 6, r = idx & 63;
        float cr = (float)r * (CUTOFF / 63.0f);
        float t = (de_s[e] - cr) / RBF_W;
        float t2 = t * t;
        Rs[idx] = (t2 < 96.0f) ? expf(-0.5f * t2) : 0.0f;
    }
    if (tid == 0) {
        int c = 0;
        for (int e = 0; e < KNBR; e++) if (de_s[e] <= CUTOFF) c++;
        g_cnt[i] = c;
    }
    __syncthreads();

    int w = tid >> 5, l = tid & 31;
    int zi = g_z[i];
    const float4* ei  = (const float4*)(g_eW1 + zi * HID);
    const float4* b14 = (const float4*)b1;

    float4 a0[4], a1[4];
    #pragma unroll
    for (int rr = 0; rr < 4; rr++) {
        int zn = g_z[nbr_s[4 * w + rr]];
        const float4* en = (const float4*)(g_eW1 + zn * HID);
        float4 u = ei[l], v = en[l], bb = b14[l];
        a0[rr] = make_float4(u.x + v.x + bb.x, u.y + v.y + bb.y,
                             u.z + v.z + bb.z, u.w + v.w + bb.w);
        u = ei[32 + l]; v = en[32 + l]; bb = b14[32 + l];
        a1[rr] = make_float4(u.x + v.x + bb.x, u.y + v.y + bb.y,
                             u.z + v.z + bb.z, u.w + v.w + bb.w);
    }
    const float* rs_w = Rs + (4 * w) * NRBF;
    for (int k = 0; k < NRBF; k++) {
        float rv0 = rs_w[k];
        float rv1 = rs_w[NRBF + k];
        float rv2 = rs_w[2 * NRBF + k];
        float rv3 = rs_w[3 * NRBF + k];
        if (rv0 + rv1 + rv2 + rv3 > 0.0f) {
            const float4* wr = (const float4*)(g_WW + k * HID);
            float4 w0 = wr[l], w1v = wr[32 + l];
            a0[0].x += rv0 * w0.x;  a0[0].y += rv0 * w0.y;
            a0[0].z += rv0 * w0.z;  a0[0].w += rv0 * w0.w;
            a1[0].x += rv0 * w1v.x; a1[0].y += rv0 * w1v.y;
            a1[0].z += rv0 * w1v.z; a1[0].w += rv0 * w1v.w;
            a0[1].x += rv1 * w0.x;  a0[1].y += rv1 * w0.y;
            a0[1].z += rv1 * w0.z;  a0[1].w += rv1 * w0.w;
            a1[1].x += rv1 * w1v.x; a1[1].y += rv1 * w1v.y;
            a1[1].z += rv1 * w1v.z; a1[1].w += rv1 * w1v.w;
            a0[2].x += rv2 * w0.x;  a0[2].y += rv2 * w0.y;
            a0[2].z += rv2 * w0.z;  a0[2].w += rv2 * w0.w;
            a1[2].x += rv2 * w1v.x; a1[2].y += rv2 * w1v.y;
            a1[2].z += rv2 * w1v.z; a1[2].w += rv2 * w1v.w;
            a0[3].x += rv3 * w0.x;  a0[3].y += rv3 * w0.y;
            a0[3].z += rv3 * w0.z;  a0[3].w += rv3 * w0.w;
            a1[3].x += rv3 * w1v.x; a1[3].y += rv3 * w1v.y;
            a1[3].z += rv3 * w1v.z; a1[3].w += rv3 * w1v.w;
        }
    }
    float4 c0 = make_float4(0, 0, 0, 0), c1 = make_float4(0, 0, 0, 0);
    #pragma unroll
    for (int rr = 0; rr < 4; rr++) {
        if (de_s[4 * w + rr] <= CUTOFF) {
            c0.x += a0[rr].x / (1.0f + expf(-a0[rr].x));
            c0.y += a0[rr].y / (1.0f + expf(-a0[rr].y));
            c0.z += a0[rr].z / (1.0f + expf(-a0[rr].z));
            c0.w += a0[rr].w / (1.0f + expf(-a0[rr].w));
            c1.x += a1[rr].x / (1.0f + expf(-a1[rr].x));
            c1.y += a1[rr].y / (1.0f + expf(-a1[rr].y));
            c1.z += a1[rr].z / (1.0f + expf(-a1[rr].z));
            c1.w += a1[rr].w / (1.0f + expf(-a1[rr].w));
        }
    }
    ((float4*)(part + w * HID))[l]      = c0;
    ((float4*)(part + w * HID))[32 + l] = c1;
    __syncthreads();
    float s = 0.0f;
    #pragma unroll
    for (int ww = 0; ww < 8; ww++) s += part[ww * HID + tid];
    g_S[(size_t)i * HID + tid] = s;
}

// ---------------- kernel 6: feat = h + S@W2 + cnt*b2, plus masks ----------------
__global__ void __launch_bounds__(256) k_final(const float* __restrict__ embed,
                                               const float* __restrict__ W2,
                                               const float* __restrict__ b2,
                                               float* __restrict__ out,
                                               int out_size) {
    int base = blockIdx.x * 32;
    int tid = threadIdx.x, w = tid >> 5, l = tid & 31;
    __shared__ float Ssm[32 * HID];
    for (int idx = tid; idx < 32 * HID; idx += 256)
        Ssm[idx] = g_S[(size_t)(base + (idx >> 8)) * HID + (idx & 255)];
    __syncthreads();

    float4 y0[4], y1[4];
    #pragma unroll
    for (int rr = 0; rr < 4; rr++) {
        y0[rr] = make_float4(0, 0, 0, 0);
        y1[rr] = make_float4(0, 0, 0, 0);
    }
    #pragma unroll 4
    for (int k = 0; k < HID; k++) {
        const float4* w2row = (const float4*)(W2 + k * HID);
        float4 wa = w2row[l], wb = w2row[32 + l];
        #pragma unroll
        for (int rr = 0; rr < 4; rr++) {
            float sv = Ssm[(4 * w + rr) * HID + k];
            y0[rr].x += sv * wa.x; y0[rr].y += sv * wa.y;
            y0[rr].z += sv * wa.z; y0[rr].w += sv * wa.w;
            y1[rr].x += sv * wb.x; y1[rr].y += sv * wb.y;
            y1[rr].z += sv * wb.z; y1[rr].w += sv * wb.w;
        }
    }
    const float4* b24 = (const float4*)b2;
    float4 ba = b24[l], bb = b24[32 + l];
    #pragma unroll
    for (int rr = 0; rr < 4; rr++) {
        int n = base + 4 * w + rr;
        int valid = g_valid[n];
        float cnt = (float)g_cnt[n];
        const float4* e4 = (const float4*)(embed + (size_t)g_z[n] * HID);
        float4 ea = e4[l], eb = e4[32 + l];
        float4 oa = make_float4(0, 0, 0, 0), ob = make_float4(0, 0, 0, 0);
        if (valid) {
            oa = make_float4(ea.x + y0[rr].x + cnt * ba.x,
                             ea.y + y0[rr].y + cnt * ba.y,
                             ea.z + y0[rr].z + cnt * ba.z,
                             ea.w + y0[rr].w + cnt * ba.w);
            ob = make_float4(eb.x + y1[rr].x + cnt * bb.x,
                             eb.y + y1[rr].y + cnt * bb.y,
                             eb.z + y1[rr].z + cnt * bb.z,
                             eb.w + y1[rr].w + cnt * bb.w);
        }
        ((float4*)(out + (size_t)n * HID))[l]      = oa;
        ((float4*)(out + (size_t)n * HID))[32 + l] = ob;
    }
    if (tid < 32 && out_size >= N_TOT * HID + 2 * N_TOT) {
        int n = base + tid;
        out[N_TOT * HID + n] = (n >= N_ATOMS && g_valid[n]) ? 1.0f : 0.0f;
        out[N_TOT * HID + N_TOT + n] = (n < N_ATOMS) ? 1.0f : 0.0f;
    }
}

// ---------------- launcher ----------------
extern "C" void kernel_launch(void* const* d_in, const int* in_sizes, int n_in,
                              void* d_out, int out_size) {
    const float* pos   = (const float*)d_in[0];
    const int*   an    = (const int*)  d_in[1];
    const float* cell  = (const float*)d_in[2];
    const float* embed = (const float*)d_in[3];
    const float* Wrbf  = (const float*)d_in[4];
    const float* W1    = (const float*)d_in[5];
    const float* b1    = (const float*)d_in[6];
    const float* W2    = (const float*)d_in[7];
    const float* b2    = (const float*)d_in[8];
    float* out = (float*)d_out;

    k_setup<<<(N_TOT + 255) / 256, 256>>>(pos, an, cell);
    k_vmask<<<N_GRID, 256>>>();
    k_pre<<<NEMB + NRBF, 256>>>(embed, Wrbf, W1);
    k_topk<<<N_TOT, 256>>>();
    k_msg<<<N_TOT, 256>>>(b1);
    k_final<<<N_TOT / 32, 256>>>(embed, W2, b2, out, out_size);
}

// round 6
// speedup vs baseline: 4.5611x; 1.0370x over previous
#include <cuda_runtime.h>
#include <math.h>

#define N_ATOMS 4096
#define NG      12
#define N_GRID  1728
#define N_TOT   5824
#define HID     256
#define KNBR    32
#define NRBF    64
#define CUTOFF  12.0f
#define RBF_W   (CUTOFF / (float)NRBF)
#define BIGD    1e9f
#define VNODE_Z 120
#define NEMB    125
#define MAXC    1536
#define NBIN    128
#define BINCAP  256
#define U64MAX  0xFFFFFFFFFFFFFFFFull
#define NCELL   8
#define NCELL3  512
#define CSIZE   5.0f

// ---------------- device scratch ----------------
__device__ float4 g_pos4[N_TOT];
__device__ int    g_valid[N_TOT];
__device__ int    g_z[N_TOT];
__device__ int    g_nbr[N_TOT * KNBR];
__device__ float  g_dedge[N_TOT * KNBR];
__device__ float  g_eW1[NEMB * HID];
__device__ float  g_WW[NRBF * HID];
__device__ float  g_S[N_TOT * HID];
__device__ int    g_cnt[N_TOT];
__device__ int    g_cellcnt[NCELL3];
__device__ int    g_cellstart[NCELL3 + 1];
__device__ int    g_cellfill[NCELL3];
__device__ int    g_cellnodes[N_TOT];

__device__ __forceinline__ int cell_of(float x, float y, float z) {
    int ix = min(NCELL - 1, max(0, (int)(x / CSIZE)));
    int iy = min(NCELL - 1, max(0, (int)(y / CSIZE)));
    int iz = min(NCELL - 1, max(0, (int)(z / CSIZE)));
    return (ix * NCELL + iy) * NCELL + iz;
}

// min squared distance from point to cell box (geometric lower bound)
__device__ __forceinline__ float cell_mind2(int c, float px, float py, float pz) {
    int ix = c / (NCELL * NCELL), iy = (c / NCELL) % NCELL, iz = c % NCELL;
    float lx = ix * CSIZE, ly = iy * CSIZE, lz = iz * CSIZE;
    float dx = fmaxf(0.0f, fmaxf(lx - px, px - (lx + CSIZE)));
    float dy = fmaxf(0.0f, fmaxf(ly - py, py - (ly + CSIZE)));
    float dz = fmaxf(0.0f, fmaxf(lz - pz, pz - (lz + CSIZE)));
    return dx * dx + dy * dy + dz * dz;
}

// ---------------- kernel 1: setup + zero cell counts ----------------
__global__ void k_setup(const float* __restrict__ pos,
                        const int* __restrict__ an,
                        const float* __restrict__ cell) {
    int i = blockIdx.x * blockDim.x + threadIdx.x;
    if (i < NCELL3) g_cellcnt[i] = 0;
    if (i >= N_TOT) return;
    float x, y, z;
    if (i < N_ATOMS) {
        x = pos[3 * i + 0]; y = pos[3 * i + 1]; z = pos[3 * i + 2];
        g_valid[i] = 1;
        g_z[i] = an[i];
    } else {
        int g = i - N_ATOMS;
        int ix = g / (NG * NG), iy = (g / NG) % NG, iz = g % NG;
        float f0 = (float)ix / (float)NG;
        float f1 = (float)iy / (float)NG;
        float f2 = (float)iz / (float)NG;
        x = f0 * cell[0] + f1 * cell[3] + f2 * cell[6];
        y = f0 * cell[1] + f1 * cell[4] + f2 * cell[7];
        z = f0 * cell[2] + f1 * cell[5] + f2 * cell[8];
        g_z[i] = VNODE_Z;
    }
    g_pos4[i] = make_float4(x, y, z, x * x + y * y + z * z);
}

// ---------------- cell list build ----------------
__global__ void k_cellcount() {
    int i = blockIdx.x * blockDim.x + threadIdx.x;
    if (i >= N_TOT) return;
    float4 p = g_pos4[i];
    atomicAdd(&g_cellcnt[cell_of(p.x, p.y, p.z)], 1);
}

__global__ void __launch_bounds__(NCELL3) k_cellscan() {
    __shared__ int tmp[NCELL3];
    int t = threadIdx.x;
    int v = g_cellcnt[t];
    tmp[t] = v;
    __syncthreads();
    for (int off = 1; off < NCELL3; off <<= 1) {
        int x = (t >= off) ? tmp[t - off] : 0;
        __syncthreads();
        tmp[t] += x;
        __syncthreads();
    }
    int excl = tmp[t] - v;
    g_cellstart[t] = excl;
    g_cellfill[t] = excl;
    if (t == NCELL3 - 1) g_cellstart[NCELL3] = tmp[t];
}

__global__ void k_cellscatter() {
    int i = blockIdx.x * blockDim.x + threadIdx.x;
    if (i >= N_TOT) return;
    float4 p = g_pos4[i];
    int pp = atomicAdd(&g_cellfill[cell_of(p.x, p.y, p.z)], 1);
    g_cellnodes[pp] = i;
}

// ---------------- kernel 2: vnode repulsion mask (cell-accelerated) ----------------
__global__ void __launch_bounds__(256) k_vmask() {
    int i = N_ATOMS + blockIdx.x;
    int tid = threadIdx.x;
    __shared__ int pcell[64];
    __shared__ int poff[65];
    __shared__ int npass_s, M_s;
    __shared__ float wm[8];
    if (tid == 0) npass_s = 0;
    __syncthreads();
    float4 p = g_pos4[i];
    for (int c = tid; c < NCELL3; c += 256) {
        if (g_cellcnt[c] > 0 && cell_mind2(c, p.x, p.y, p.z) <= 4.01f) {
            int q = atomicAdd(&npass_s, 1);
            if (q < 64) pcell[q] = c;
        }
    }
    __syncthreads();
    if (tid == 0) {
        int np = min(npass_s, 64);
        int acc = 0;
        for (int q = 0; q < np; q++) { poff[q] = acc; acc += g_cellcnt[pcell[q]]; }
        poff[np] = acc;
        M_s = acc;
        npass_s = np;
    }
    __syncthreads();
    int M = M_s, np = npass_s;
    float m = 3e38f;
    for (int t = tid; t < M; t += 256) {
        int lo = 0, hi = np - 1;
        while (lo < hi) { int mid = (lo + hi + 1) >> 1; if (poff[mid] <= t) lo = mid; else hi = mid - 1; }
        int pc = pcell[lo];
        int j = g_cellnodes[g_cellstart[pc] + (t - poff[lo])];
        if (j < N_ATOMS) {
            float4 q = g_pos4[j];
            float d2 = p.w + q.w - 2.0f * (p.x * q.x + p.y * q.y + p.z * q.z);
            m = fminf(m, d2);
        }
    }
    #pragma unroll
    for (int o = 16; o; o >>= 1) m = fminf(m, __shfl_xor_sync(0xffffffffu, m, o));
    if ((tid & 31) == 0) wm[tid >> 5] = m;
    __syncthreads();
    if (tid == 0) {
        float b = wm[0];
        #pragma unroll
        for (int w = 1; w < 8; w++) b = fminf(b, wm[w]);
        g_valid[i] = (b >= 4.0f) ? 1 : 0;
    }
}

// ---------------- kernel 3: merged precompute ----------------
__global__ void __launch_bounds__(256) k_pre(const float* __restrict__ embed,
                                             const float* __restrict__ Wrbf,
                                             const float* __restrict__ W1) {
    int r = blockIdx.x, c = threadIdx.x;
    const float* A = (r < NEMB) ? (embed + (size_t)r * HID)
                                : (Wrbf + (size_t)(r - NEMB) * HID);
    float a0 = 0.f, a1 = 0.f, a2 = 0.f, a3 = 0.f;
    #pragma unroll 8
    for (int k = 0; k < HID; k += 4) {
        a0 += A[k + 0] * W1[(k + 0) * HID + c];
        a1 += A[k + 1] * W1[(k + 1) * HID + c];
        a2 += A[k + 2] * W1[(k + 2) * HID + c];
        a3 += A[k + 3] * W1[(k + 3) * HID + c];
    }
    float acc = (a0 + a1) + (a2 + a3);
    if (r < NEMB) g_eW1[r * HID + c] = acc;
    else          g_WW[(r - NEMB) * HID + c] = acc;
}

// ---------------- kernel 4: cell-accelerated histogram-select top-K ----------------
__global__ void __launch_bounds__(256) k_topk() {
    int i = blockIdx.x, tid = threadIdx.x;
    __shared__ unsigned long long cand[MAXC];
    __shared__ unsigned long long binbuf[BINCAP];
    __shared__ unsigned long long sel[KNBR];
    __shared__ int hist[NBIN];
    __shared__ int pcell[NCELL3];
    __shared__ int poff[NCELL3 + 1];
    __shared__ int ncand, nsel, nbin, s_B, npass_s, M_s;
    if (!g_valid[i]) {
        if (tid < KNBR) { g_nbr[i * KNBR + tid] = 0; g_dedge[i * KNBR + tid] = BIGD; }
        return;
    }
    if (tid == 0) { ncand = 0; nsel = 0; nbin = 0; npass_s = 0; }
    if (tid < NBIN) hist[tid] = 0;
    __syncthreads();

    float4 p = g_pos4[i];
    int lane = tid & 31;

    // --- phase A0: passing cells (box mindist^2 <= 145.5) ---
    for (int c = tid; c < NCELL3; c += 256) {
        if (g_cellcnt[c] > 0 && cell_mind2(c, p.x, p.y, p.z) <= 145.5f) {
            pcell[atomicAdd(&npass_s, 1)] = c;
        }
    }
    __syncthreads();
    if (tid == 0) {
        int np = npass_s, acc = 0;
        for (int q = 0; q < np; q++) { poff[q] = acc; acc += g_cellcnt[pcell[q]]; }
        poff[np] = acc;
        M_s = acc;
    }
    __syncthreads();
    int M = M_s, np = npass_s;
    int Mr = (M + 255) & ~255;

    // --- phase A: flattened sweep + candidate compaction (d2 <= 145) ---
    for (int t = tid; t < Mr; t += 256) {
        bool keep = false;
        float d2 = 0.0f;
        int j = -1;
        if (t < M) {
            int lo = 0, hi = np - 1;
            while (lo < hi) { int mid = (lo + hi + 1) >> 1; if (poff[mid] <= t) lo = mid; else hi = mid - 1; }
            int pc = pcell[lo];
            j = g_cellnodes[g_cellstart[pc] + (t - poff[lo])];
            float4 q = g_pos4[j];
            d2 = p.w + q.w - 2.0f * (p.x * q.x + p.y * q.y + p.z * q.z);
            keep = (d2 <= 145.0f) && (j != i) && (g_valid[j] != 0);
        }
        unsigned m = __ballot_sync(0xffffffffu, keep);
        int cpos = 0;
        if (lane == 0) cpos = m ? atomicAdd(&ncand, __popc(m)) : 0;
        cpos = __shfl_sync(0xffffffffu, cpos, 0);
        if (keep) {
            int off = cpos + __popc(m & ((1u << lane) - 1u));
            if (off < MAXC)
                cand[off] = ((unsigned long long)__float_as_uint(fmaxf(d2, 0.0f)) << 32)
                            | (unsigned)j;
        }
    }
    __syncthreads();
    int nc = min(ncand, MAXC);

    if (nc <= KNBR) {
        if (tid < KNBR) sel[tid] = (tid < nc) ? cand[tid] : U64MAX;
        __syncthreads();
    } else {
        // --- phase B: histogram over d2 ---
        for (int idx = tid; idx < nc; idx += 256) {
            float d2 = __uint_as_float((unsigned)(cand[idx] >> 32));
            int b = min(NBIN - 1, (int)(d2 * ((float)NBIN / 145.0f)));
            atomicAdd(&hist[b], 1);
        }
        __syncthreads();
        if (tid == 0) {
            int c = 0, B = NBIN - 1;
            for (int b = 0; b < NBIN; b++) {
                if (c + hist[b] >= KNBR) { B = b; break; }
                c += hist[b];
            }
            s_B = B;
        }
        __syncthreads();
        int B = s_B;
        // --- phase C: split ---
        for (int idx = tid; idx < nc; idx += 256) {
            unsigned long long key = cand[idx];
            float d2 = __uint_as_float((unsigned)(key >> 32));
            int b = min(NBIN - 1, (int)(d2 * ((float)NBIN / 145.0f)));
            if (b < B) {
                sel[atomicAdd(&nsel, 1)] = key;
            } else if (b == B) {
                int pp = atomicAdd(&nbin, 1);
                if (pp < BINCAP) binbuf[pp] = key;
            }
        }
        __syncthreads();
        if (tid == 0) {
            int have = nsel;
            int m = KNBR - have;
            int bc = min(nbin, BINCAP);
            for (int s = 0; s < m; s++) {
                unsigned long long best = U64MAX;
                int bi = -1;
                for (int t = 0; t < bc; t++)
                    if (binbuf[t] < best) { best = binbuf[t]; bi = t; }
                if (bi >= 0) binbuf[bi] = U64MAX;
                sel[have + s] = best;
            }
        }
        __syncthreads();
    }

    // --- phase D: warp-0 bitonic sort + write out ---
    if (tid < 32) {
        unsigned long long v = sel[tid];
        #pragma unroll
        for (int k = 2; k <= 32; k <<= 1) {
            #pragma unroll
            for (int j = k >> 1; j > 0; j >>= 1) {
                unsigned long long o = __shfl_xor_sync(0xffffffffu, v, j);
                bool up = ((tid & k) == 0);
                bool lower = ((tid & j) == 0);
                unsigned long long mn = min(v, o), mx = max(v, o);
                v = (up == lower) ? mn : mx;
            }
        }
        if (v == U64MAX) {
            g_nbr[i * KNBR + tid] = 0;
            g_dedge[i * KNBR + tid] = BIGD;
        } else {
            g_nbr[i * KNBR + tid] = (int)(v & 0xFFFFFFFFull);
            float d2 = __uint_as_float((unsigned)(v >> 32));
            g_dedge[i * KNBR + tid] = sqrtf(fmaxf(d2, 1e-12f));
        }
    }
}

// ---------------- kernel 5: per-edge messages, sparse RBF ----------------
__global__ void __launch_bounds__(256) k_msg(const float* __restrict__ b1) {
    int i = blockIdx.x, tid = threadIdx.x;
    if (!g_valid[i]) {
        g_S[(size_t)i * HID + tid] = 0.0f;
        if (tid == 0) g_cnt[i] = 0;
        return;
    }
    __shared__ float Rs[KNBR * NRBF];
    __shared__ float part[8 * HID];
    __shared__ int   nbr_s[KNBR];
    __shared__ float de_s[KNBR];
    if (tid < KNBR) {
        nbr_s[tid] = g_nbr[i * KNBR + tid];
        de_s[tid]  = g_dedge[i * KNBR + tid];
    }
    __syncthreads();
    for (int idx = tid; idx < KNBR * NRBF; idx += 256) {
        int e = idx >> 6, r = idx & 63;
        float cr = (float)r * (CUTOFF / 63.0f);
        float t = (de_s[e] - cr) / RBF_W;
        float t2 = t * t;
        // exp(-16) ~ 1.1e-7 -> negligible; hard zero enables warp-uniform skip
        Rs[idx] = (t2 < 32.0f) ? expf(-0.5f * t2) : 0.0f;
    }
    if (tid == 0) {
        int c = 0;
        for (int e = 0; e < KNBR; e++) if (de_s[e] <= CUTOFF) c++;
        g_cnt[i] = c;
    }
    __syncthreads();

    int w = tid >> 5, l = tid & 31;
    int zi = g_z[i];
    const float4* ei  = (const float4*)(g_eW1 + zi * HID);
    const float4* b14 = (const float4*)b1;

    float4 a0[4], a1[4];
    #pragma unroll
    for (int rr = 0; rr < 4; rr++) {
        int zn = g_z[nbr_s[4 * w + rr]];
        const float4* en = (const float4*)(g_eW1 + zn * HID);
        float4 u = ei[l], v = en[l], bb = b14[l];
        a0[rr] = make_float4(u.x + v.x + bb.x, u.y + v.y + bb.y,
                             u.z + v.z + bb.z, u.w + v.w + bb.w);
        u = ei[32 + l]; v = en[32 + l]; bb = b14[32 + l];
        a1[rr] = make_float4(u.x + v.x + bb.x, u.y + v.y + bb.y,
                             u.z + v.z + bb.z, u.w + v.w + bb.w);
    }
    const float* rs_w = Rs + (4 * w) * NRBF;
    for (int k = 0; k < NRBF; k++) {
        float rv0 = rs_w[k];
        float rv1 = rs_w[NRBF + k];
        float rv2 = rs_w[2 * NRBF + k];
        float rv3 = rs_w[3 * NRBF + k];
        if (rv0 + rv1 + rv2 + rv3 > 0.0f) {
            const float4* wr = (const float4*)(g_WW + k * HID);
            float4 w0 = wr[l], w1v = wr[32 + l];
            a0[0].x += rv0 * w0.x;  a0[0].y += rv0 * w0.y;
            a0[0].z += rv0 * w0.z;  a0[0].w += rv0 * w0.w;
            a1[0].x += rv0 * w1v.x; a1[0].y += rv0 * w1v.y;
            a1[0].z += rv0 * w1v.z; a1[0].w += rv0 * w1v.w;
            a0[1].x += rv1 * w0.x;  a0[1].y += rv1 * w0.y;
            a0[1].z += rv1 * w0.z;  a0[1].w += rv1 * w0.w;
            a1[1].x += rv1 * w1v.x; a1[1].y += rv1 * w1v.y;
            a1[1].z += rv1 * w1v.z; a1[1].w += rv1 * w1v.w;
            a0[2].x += rv2 * w0.x;  a0[2].y += rv2 * w0.y;
            a0[2].z += rv2 * w0.z;  a0[2].w += rv2 * w0.w;
            a1[2].x += rv2 * w1v.x; a1[2].y += rv2 * w1v.y;
            a1[2].z += rv2 * w1v.z; a1[2].w += rv2 * w1v.w;
            a0[3].x += rv3 * w0.x;  a0[3].y += rv3 * w0.y;
            a0[3].z += rv3 * w0.z;  a0[3].w += rv3 * w0.w;
            a1[3].x += rv3 * w1v.x; a1[3].y += rv3 * w1v.y;
            a1[3].z += rv3 * w1v.z; a1[3].w += rv3 * w1v.w;
        }
    }
    float4 c0 = make_float4(0, 0, 0, 0), c1 = make_float4(0, 0, 0, 0);
    #pragma unroll
    for (int rr = 0; rr < 4; rr++) {
        if (de_s[4 * w + rr] <= CUTOFF) {
            c0.x += a0[rr].x / (1.0f + expf(-a0[rr].x));
            c0.y += a0[rr].y / (1.0f + expf(-a0[rr].y));
            c0.z += a0[rr].z / (1.0f + expf(-a0[rr].z));
            c0.w += a0[rr].w / (1.0f + expf(-a0[rr].w));
            c1.x += a1[rr].x / (1.0f + expf(-a1[rr].x));
            c1.y += a1[rr].y / (1.0f + expf(-a1[rr].y));
            c1.z += a1[rr].z / (1.0f + expf(-a1[rr].z));
            c1.w += a1[rr].w / (1.0f + expf(-a1[rr].w));
        }
    }
    ((float4*)(part + w * HID))[l]      = c0;
    ((float4*)(part + w * HID))[32 + l] = c1;
    __syncthreads();
    float s = 0.0f;
    #pragma unroll
    for (int ww = 0; ww < 8; ww++) s += part[ww * HID + tid];
    g_S[(size_t)i * HID + tid] = s;
}

// ---------------- kernel 6: feat = h + S@W2 + cnt*b2, plus masks ----------------
__global__ void __launch_bounds__(256) k_final(const float* __restrict__ embed,
                                               const float* __restrict__ W2,
                                               const float* __restrict__ b2,
                                               float* __restrict__ out,
                                               int out_size) {
    int base = blockIdx.x * 32;
    int tid = threadIdx.x, w = tid >> 5, l = tid & 31;
    __shared__ float Ssm[32 * HID];
    for (int idx = tid; idx < 32 * HID; idx += 256)
        Ssm[idx] = g_S[(size_t)(base + (idx >> 8)) * HID + (idx & 255)];
    __syncthreads();

    float4 y0[4], y1[4];
    #pragma unroll
    for (int rr = 0; rr < 4; rr++) {
        y0[rr] = make_float4(0, 0, 0, 0);
        y1[rr] = make_float4(0, 0, 0, 0);
    }
    #pragma unroll 4
    for (int k = 0; k < HID; k++) {
        const float4* w2row = (const float4*)(W2 + k * HID);
        float4 wa = w2row[l], wb = w2row[32 + l];
        #pragma unroll
        for (int rr = 0; rr < 4; rr++) {
            float sv = Ssm[(4 * w + rr) * HID + k];
            y0[rr].x += sv * wa.x; y0[rr].y += sv * wa.y;
            y0[rr].z += sv * wa.z; y0[rr].w += sv * wa.w;
            y1[rr].x += sv * wb.x; y1[rr].y += sv * wb.y;
            y1[rr].z += sv * wb.z; y1[rr].w += sv * wb.w;
        }
    }
    const float4* b24 = (const float4*)b2;
    float4 ba = b24[l], bb = b24[32 + l];
    #pragma unroll
    for (int rr = 0; rr < 4; rr++) {
        int n = base + 4 * w + rr;
        int valid = g_valid[n];
        float cnt = (float)g_cnt[n];
        const float4* e4 = (const float4*)(embed + (size_t)g_z[n] * HID);
        float4 ea = e4[l], eb = e4[32 + l];
        float4 oa = make_float4(0, 0, 0, 0), ob = make_float4(0, 0, 0, 0);
        if (valid) {
            oa = make_float4(ea.x + y0[rr].x + cnt * ba.x,
                             ea.y + y0[rr].y + cnt * ba.y,
                             ea.z + y0[rr].z + cnt * ba.z,
                             ea.w + y0[rr].w + cnt * ba.w);
            ob = make_float4(eb.x + y1[rr].x + cnt * bb.x,
                             eb.y + y1[rr].y + cnt * bb.y,
                             eb.z + y1[rr].z + cnt * bb.z,
                             eb.w + y1[rr].w + cnt * bb.w);
        }
        ((float4*)(out + (size_t)n * HID))[l]      = oa;
        ((float4*)(out + (size_t)n * HID))[32 + l] = ob;
    }
    if (tid < 32 && out_size >= N_TOT * HID + 2 * N_TOT) {
        int n = base + tid;
        out[N_TOT * HID + n] = (n >= N_ATOMS && g_valid[n]) ? 1.0f : 0.0f;
        out[N_TOT * HID + N_TOT + n] = (n < N_ATOMS) ? 1.0f : 0.0f;
    }
}

// ---------------- launcher ----------------
extern "C" void kernel_launch(void* const* d_in, const int* in_sizes, int n_in,
                              void* d_out, int out_size) {
    const float* pos   = (const float*)d_in[0];
    const int*   an    = (const int*)  d_in[1];
    const float* cell  = (const float*)d_in[2];
    const float* embed = (const float*)d_in[3];
    const float* Wrbf  = (const float*)d_in[4];
    const float* W1    = (const float*)d_in[5];
    const float* b1    = (const float*)d_in[6];
    const float* W2    = (const float*)d_in[7];
    const float* b2    = (const float*)d_in[8];
    float* out = (float*)d_out;

    k_setup<<<(N_TOT + 255) / 256, 256>>>(pos, an, cell);
    k_cellcount<<<(N_TOT + 255) / 256, 256>>>();
    k_cellscan<<<1, NCELL3>>>();
    k_cellscatter<<<(N_TOT + 255) / 256, 256>>>();
    k_vmask<<<N_GRID, 256>>>();
    k_pre<<<NEMB + NRBF, 256>>>(embed, Wrbf, W1);
    k_topk<<<N_TOT, 256>>>();
    k_msg<<<N_TOT, 256>>>(b1);
    k_final<<<N_TOT / 32, 256>>>(embed, W2, b2, out, out_size);
}

// round 7
// speedup vs baseline: 5.5230x; 1.2109x over previous
#include <cuda_runtime.h>
#include <math.h>

#define N_ATOMS 4096
#define NG      12
#define N_GRID  1728
#define N_TOT   5824
#define HID     256
#define KNBR    32
#define NRBF    64
#define CUTOFF  12.0f
#define RBF_W   (CUTOFF / (float)NRBF)
#define RBF_STEP (CUTOFF / 63.0f)
#define BIGD    1e9f
#define VNODE_Z 120
#define NEMB    125
#define MAXC    1536
#define NBIN    128
#define BINCAP  256
#define U64MAX  0xFFFFFFFFFFFFFFFFull
#define NCELL   8
#define NCELL3  512
#define CSIZE   5.0f

// ---------------- device scratch ----------------
__device__ float4 g_pos4[N_TOT];
__device__ int    g_valid[N_TOT];
__device__ int    g_z[N_TOT];
__device__ int    g_nbr[N_TOT * KNBR];
__device__ float  g_dedge[N_TOT * KNBR];
__device__ float  g_eW1[NEMB * HID];
__device__ float  g_WW[NRBF * HID];
__device__ float  g_S[N_TOT * HID];
__device__ int    g_cnt[N_TOT];
__device__ int    g_cellcnt[NCELL3];
__device__ int    g_cellstart[NCELL3];
__device__ int    g_cellnodes[N_TOT];

__device__ __forceinline__ int cell_of(float x, float y, float z) {
    int ix = min(NCELL - 1, max(0, (int)(x / CSIZE)));
    int iy = min(NCELL - 1, max(0, (int)(y / CSIZE)));
    int iz = min(NCELL - 1, max(0, (int)(z / CSIZE)));
    return (ix * NCELL + iy) * NCELL + iz;
}

__device__ __forceinline__ float cell_mind2(int c, float px, float py, float pz) {
    int ix = c / (NCELL * NCELL), iy = (c / NCELL) % NCELL, iz = c % NCELL;
    float lx = ix * CSIZE, ly = iy * CSIZE, lz = iz * CSIZE;
    float dx = fmaxf(0.0f, fmaxf(lx - px, px - (lx + CSIZE)));
    float dy = fmaxf(0.0f, fmaxf(ly - py, py - (ly + CSIZE)));
    float dz = fmaxf(0.0f, fmaxf(lz - pz, pz - (lz + CSIZE)));
    return dx * dx + dy * dy + dz * dz;
}

// ---------------- kernel 1: setup + zero cell counts ----------------
__global__ void k_setup(const float* __restrict__ pos,
                        const int* __restrict__ an,
                        const float* __restrict__ cell) {
    int i = blockIdx.x * blockDim.x + threadIdx.x;
    if (i < NCELL3) g_cellcnt[i] = 0;
    if (i >= N_TOT) return;
    float x, y, z;
    if (i < N_ATOMS) {
        x = pos[3 * i + 0]; y = pos[3 * i + 1]; z = pos[3 * i + 2];
        g_valid[i] = 1;
        g_z[i] = an[i];
    } else {
        int g = i - N_ATOMS;
        int ix = g / (NG * NG), iy = (g / NG) % NG, iz = g % NG;
        float f0 = (float)ix / (float)NG;
        float f1 = (float)iy / (float)NG;
        float f2 = (float)iz / (float)NG;
        x = f0 * cell[0] + f1 * cell[3] + f2 * cell[6];
        y = f0 * cell[1] + f1 * cell[4] + f2 * cell[7];
        z = f0 * cell[2] + f1 * cell[5] + f2 * cell[8];
        g_z[i] = VNODE_Z;
    }
    g_pos4[i] = make_float4(x, y, z, x * x + y * y + z * z);
}

__global__ void k_cellcount() {
    int i = blockIdx.x * blockDim.x + threadIdx.x;
    if (i >= N_TOT) return;
    float4 p = g_pos4[i];
    atomicAdd(&g_cellcnt[cell_of(p.x, p.y, p.z)], 1);
}

// single block: scan + scatter (smem fill counters)
__global__ void __launch_bounds__(NCELL3) k_cellbuild() {
    __shared__ int tmp[NCELL3];
    __shared__ int fill[NCELL3];
    int t = threadIdx.x;
    int v = g_cellcnt[t];
    tmp[t] = v;
    __syncthreads();
    for (int off = 1; off < NCELL3; off <<= 1) {
        int x = (t >= off) ? tmp[t - off] : 0;
        __syncthreads();
        tmp[t] += x;
        __syncthreads();
    }
    int excl = tmp[t] - v;
    g_cellstart[t] = excl;
    fill[t] = excl;
    __syncthreads();
    for (int i = t; i < N_TOT; i += NCELL3) {
        float4 p = g_pos4[i];
        int pp = atomicAdd(&fill[cell_of(p.x, p.y, p.z)], 1);
        g_cellnodes[pp] = i;
    }
}

// ---------------- kernel 2: vnode repulsion mask (warp-per-cell) ----------------
__global__ void __launch_bounds__(256) k_vmask() {
    int i = N_ATOMS + blockIdx.x;
    int tid = threadIdx.x, w = tid >> 5, lane = tid & 31;
    __shared__ int pcell[64];
    __shared__ int npass_s;
    __shared__ float wm[8];
    if (tid == 0) npass_s = 0;
    __syncthreads();
    float4 p = g_pos4[i];
    for (int c = tid; c < NCELL3; c += 256) {
        if (g_cellcnt[c] > 0 && cell_mind2(c, p.x, p.y, p.z) <= 4.01f) {
            int q = atomicAdd(&npass_s, 1);
            if (q < 64) pcell[q] = c;
        }
    }
    __syncthreads();
    int np = min(npass_s, 64);
    float m = 3e38f;
    for (int q = w; q < np; q += 8) {
        int pc = pcell[q];
        int st = g_cellstart[pc], cnt = g_cellcnt[pc];
        for (int t = lane; t < cnt; t += 32) {
            int j = g_cellnodes[st + t];
            if (j < N_ATOMS) {
                float4 qq = g_pos4[j];
                float d2 = p.w + qq.w - 2.0f * (p.x * qq.x + p.y * qq.y + p.z * qq.z);
                m = fminf(m, d2);
            }
        }
    }
    #pragma unroll
    for (int o = 16; o; o >>= 1) m = fminf(m, __shfl_xor_sync(0xffffffffu, m, o));
    if (lane == 0) wm[w] = m;
    __syncthreads();
    if (tid == 0) {
        float b = wm[0];
        #pragma unroll
        for (int ww = 1; ww < 8; ww++) b = fminf(b, wm[ww]);
        g_valid[i] = (b >= 4.0f) ? 1 : 0;
    }
}

// ---------------- kernel 3: merged precompute ----------------
__global__ void __launch_bounds__(256) k_pre(const float* __restrict__ embed,
                                             const float* __restrict__ Wrbf,
                                             const float* __restrict__ W1) {
    int r = blockIdx.x, c = threadIdx.x;
    const float* A = (r < NEMB) ? (embed + (size_t)r * HID)
                                : (Wrbf + (size_t)(r - NEMB) * HID);
    float a0 = 0.f, a1 = 0.f, a2 = 0.f, a3 = 0.f;
    #pragma unroll 8
    for (int k = 0; k < HID; k += 4) {
        a0 += A[k + 0] * W1[(k + 0) * HID + c];
        a1 += A[k + 1] * W1[(k + 1) * HID + c];
        a2 += A[k + 2] * W1[(k + 2) * HID + c];
        a3 += A[k + 3] * W1[(k + 3) * HID + c];
    }
    float acc = (a0 + a1) + (a2 + a3);
    if (r < NEMB) g_eW1[r * HID + c] = acc;
    else          g_WW[(r - NEMB) * HID + c] = acc;
}

// ---------------- kernel 4: cell-accelerated top-K (warp-per-cell sweep) ----------------
__global__ void __launch_bounds__(256) k_topk() {
    int i = blockIdx.x, tid = threadIdx.x;
    int w = tid >> 5, lane = tid & 31;
    __shared__ unsigned long long cand[MAXC];
    __shared__ unsigned long long binbuf[BINCAP];
    __shared__ unsigned long long sel[KNBR];
    __shared__ int hist[NBIN];
    __shared__ int pcell[160];
    __shared__ int ncand, nsel, nbin, s_B, npass_s;
    if (!g_valid[i]) {
        if (tid < KNBR) { g_nbr[i * KNBR + tid] = 0; g_dedge[i * KNBR + tid] = BIGD; }
        return;
    }
    if (tid == 0) { ncand = 0; nsel = 0; nbin = 0; npass_s = 0; }
    if (tid < NBIN) hist[tid] = 0;
    __syncthreads();

    float4 p = g_pos4[i];

    // --- phase A0: passing cells ---
    for (int c = tid; c < NCELL3; c += 256) {
        if (g_cellcnt[c] > 0 && cell_mind2(c, p.x, p.y, p.z) <= 145.5f) {
            int q = atomicAdd(&npass_s, 1);
            if (q < 160) pcell[q] = c;
        }
    }
    __syncthreads();
    int np = min(npass_s, 160);

    // --- phase A: warp-per-cell sweep + compaction ---
    for (int q = w; q < np; q += 8) {
        int pc = pcell[q];
        int st = g_cellstart[pc], cnt = g_cellcnt[pc];
        int cr = (cnt + 31) & ~31;
        for (int t = lane; t < cr; t += 32) {
            bool keep = false;
            float d2 = 0.0f;
            int j = -1;
            if (t < cnt) {
                j = g_cellnodes[st + t];
                float4 qq = g_pos4[j];
                d2 = p.w + qq.w - 2.0f * (p.x * qq.x + p.y * qq.y + p.z * qq.z);
                keep = (d2 <= 145.0f) && (j != i) && (g_valid[j] != 0);
            }
            unsigned m = __ballot_sync(0xffffffffu, keep);
            int cpos = 0;
            if (lane == 0) cpos = m ? atomicAdd(&ncand, __popc(m)) : 0;
            cpos = __shfl_sync(0xffffffffu, cpos, 0);
            if (keep) {
                int off = cpos + __popc(m & ((1u << lane) - 1u));
                if (off < MAXC)
                    cand[off] = ((unsigned long long)__float_as_uint(fmaxf(d2, 0.0f)) << 32)
                                | (unsigned)j;
            }
        }
    }
    __syncthreads();
    int nc = min(ncand, MAXC);

    if (nc <= KNBR) {
        if (tid < KNBR) sel[tid] = (tid < nc) ? cand[tid] : U64MAX;
        __syncthreads();
    } else {
        for (int idx = tid; idx < nc; idx += 256) {
            float d2 = __uint_as_float((unsigned)(cand[idx] >> 32));
            int b = min(NBIN - 1, (int)(d2 * ((float)NBIN / 145.0f)));
            atomicAdd(&hist[b], 1);
        }
        __syncthreads();
        if (tid == 0) {
            int c = 0, B = NBIN - 1;
            for (int b = 0; b < NBIN; b++) {
                if (c + hist[b] >= KNBR) { B = b; break; }
                c += hist[b];
            }
            s_B = B;
        }
        __syncthreads();
        int B = s_B;
        for (int idx = tid; idx < nc; idx += 256) {
            unsigned long long key = cand[idx];
            float d2 = __uint_as_float((unsigned)(key >> 32));
            int b = min(NBIN - 1, (int)(d2 * ((float)NBIN / 145.0f)));
            if (b < B) {
                sel[atomicAdd(&nsel, 1)] = key;
            } else if (b == B) {
                int pp = atomicAdd(&nbin, 1);
                if (pp < BINCAP) binbuf[pp] = key;
            }
        }
        __syncthreads();
        if (tid == 0) {
            int have = nsel;
            int m = KNBR - have;
            int bc = min(nbin, BINCAP);
            for (int s = 0; s < m; s++) {
                unsigned long long best = U64MAX;
                int bi = -1;
                for (int t = 0; t < bc; t++)
                    if (binbuf[t] < best) { best = binbuf[t]; bi = t; }
                if (bi >= 0) binbuf[bi] = U64MAX;
                sel[have + s] = best;
            }
        }
        __syncthreads();
    }

    // --- phase D: warp-0 bitonic sort + write ---
    if (tid < 32) {
        unsigned long long v = sel[tid];
        #pragma unroll
        for (int k = 2; k <= 32; k <<= 1) {
            #pragma unroll
            for (int j = k >> 1; j > 0; j >>= 1) {
                unsigned long long o = __shfl_xor_sync(0xffffffffu, v, j);
                bool up = ((tid & k) == 0);
                bool lower = ((tid & j) == 0);
                unsigned long long mn = min(v, o), mx = max(v, o);
                v = (up == lower) ? mn : mx;
            }
        }
        if (v == U64MAX) {
            g_nbr[i * KNBR + tid] = 0;
            g_dedge[i * KNBR + tid] = BIGD;
        } else {
            g_nbr[i * KNBR + tid] = (int)(v & 0xFFFFFFFFull);
            float d2 = __uint_as_float((unsigned)(v >> 32));
            g_dedge[i * KNBR + tid] = sqrtf(fmaxf(d2, 1e-12f));
        }
    }
}

// ---------------- kernel 5: per-edge messages, windowed RBF + fast math ----------------
__global__ void __launch_bounds__(256) k_msg(const float* __restrict__ b1) {
    int i = blockIdx.x, tid = threadIdx.x;
    if (!g_valid[i]) {
        g_S[(size_t)i * HID + tid] = 0.0f;
        if (tid == 0) g_cnt[i] = 0;
        return;
    }
    __shared__ float Rs[KNBR * NRBF];
    __shared__ float part[8 * HID];
    __shared__ int   nbr_s[KNBR];
    __shared__ float de_s[KNBR];
    if (tid < KNBR) {
        nbr_s[tid] = g_nbr[i * KNBR + tid];
        de_s[tid]  = g_dedge[i * KNBR + tid];
    }
    __syncthreads();
    for (int idx = tid; idx < KNBR * NRBF; idx += 256) {
        int e = idx >> 6, r = idx & 63;
        float cr = (float)r * RBF_STEP;
        float t = (de_s[e] - cr) * (1.0f / RBF_W);
        float t2 = t * t;
        Rs[idx] = (t2 < 32.0f) ? __expf(-0.5f * t2) : 0.0f;
    }
    if (tid == 0) {
        int c = 0;
        for (int e = 0; e < KNBR; e++) if (de_s[e] <= CUTOFF) c++;
        g_cnt[i] = c;
    }
    __syncthreads();

    int w = tid >> 5, l = tid & 31;
    int zi = g_z[i];
    const float4* ei  = (const float4*)(g_eW1 + zi * HID);
    const float4* b14 = (const float4*)b1;

    float4 a0[4], a1[4];
    #pragma unroll
    for (int rr = 0; rr < 4; rr++) {
        int zn = g_z[nbr_s[4 * w + rr]];
        const float4* en = (const float4*)(g_eW1 + zn * HID);
        float4 u = ei[l], v = en[l], bb = b14[l];
        a0[rr] = make_float4(u.x + v.x + bb.x, u.y + v.y + bb.y,
                             u.z + v.z + bb.z, u.w + v.w + bb.w);
        u = ei[32 + l]; v = en[32 + l]; bb = b14[32 + l];
        a1[rr] = make_float4(u.x + v.x + bb.x, u.y + v.y + bb.y,
                             u.z + v.z + bb.z, u.w + v.w + bb.w);
    }

    // per-warp active RBF window from edge distances (edges sorted ascending)
    float dmin = 3e38f, dmax = -1.0f;
    #pragma unroll
    for (int rr = 0; rr < 4; rr++) {
        float d = de_s[4 * w + rr];
        if (d <= CUTOFF) { dmin = fminf(dmin, d); dmax = fmaxf(dmax, d); }
    }
    if (dmax >= 0.0f) {
        // |d - c_k| < sqrt(32)*RBF_W = 1.06066 beyond which Rs==0
        int kmin = max(0,  (int)ceilf ((dmin - 1.0607f) * (1.0f / RBF_STEP)));
        int kmax = min(63, (int)floorf((dmax + 1.0607f) * (1.0f / RBF_STEP)));
        const float* rs_w = Rs + (4 * w) * NRBF;
        for (int k = kmin; k <= kmax; k++) {
            float rv0 = rs_w[k];
            float rv1 = rs_w[NRBF + k];
            float rv2 = rs_w[2 * NRBF + k];
            float rv3 = rs_w[3 * NRBF + k];
            const float4* wr = (const float4*)(g_WW + k * HID);
            float4 w0 = wr[l], w1v = wr[32 + l];
            a0[0].x += rv0 * w0.x;  a0[0].y += rv0 * w0.y;
            a0[0].z += rv0 * w0.z;  a0[0].w += rv0 * w0.w;
            a1[0].x += rv0 * w1v.x; a1[0].y += rv0 * w1v.y;
            a1[0].z += rv0 * w1v.z; a1[0].w += rv0 * w1v.w;
            a0[1].x += rv1 * w0.x;  a0[1].y += rv1 * w0.y;
            a0[1].z += rv1 * w0.z;  a0[1].w += rv1 * w0.w;
            a1[1].x += rv1 * w1v.x; a1[1].y += rv1 * w1v.y;
            a1[1].z += rv1 * w1v.z; a1[1].w += rv1 * w1v.w;
            a0[2].x += rv2 * w0.x;  a0[2].y += rv2 * w0.y;
            a0[2].z += rv2 * w0.z;  a0[2].w += rv2 * w0.w;
            a1[2].x += rv2 * w1v.x; a1[2].y += rv2 * w1v.y;
            a1[2].z += rv2 * w1v.z; a1[2].w += rv2 * w1v.w;
            a0[3].x += rv3 * w0.x;  a0[3].y += rv3 * w0.y;
            a0[3].z += rv3 * w0.z;  a0[3].w += rv3 * w0.w;
            a1[3].x += rv3 * w1v.x; a1[3].y += rv3 * w1v.y;
            a1[3].z += rv3 * w1v.z; a1[3].w += rv3 * w1v.w;
        }
    }

    float4 c0 = make_float4(0, 0, 0, 0), c1 = make_float4(0, 0, 0, 0);
    #pragma unroll
    for (int rr = 0; rr < 4; rr++) {
        if (de_s[4 * w + rr] <= CUTOFF) {
            c0.x += __fdividef(a0[rr].x, 1.0f + __expf(-a0[rr].x));
            c0.y += __fdividef(a0[rr].y, 1.0f + __expf(-a0[rr].y));
            c0.z += __fdividef(a0[rr].z, 1.0f + __expf(-a0[rr].z));
            c0.w += __fdividef(a0[rr].w, 1.0f + __expf(-a0[rr].w));
            c1.x += __fdividef(a1[rr].x, 1.0f + __expf(-a1[rr].x));
            c1.y += __fdividef(a1[rr].y, 1.0f + __expf(-a1[rr].y));
            c1.z += __fdividef(a1[rr].z, 1.0f + __expf(-a1[rr].z));
            c1.w += __fdividef(a1[rr].w, 1.0f + __expf(-a1[rr].w));
        }
    }
    ((float4*)(part + w * HID))[l]      = c0;
    ((float4*)(part + w * HID))[32 + l] = c1;
    __syncthreads();
    float s = 0.0f;
    #pragma unroll
    for (int ww = 0; ww < 8; ww++) s += part[ww * HID + tid];
    g_S[(size_t)i * HID + tid] = s;
}

// ---------------- kernel 6: feat = h + S@W2 + cnt*b2, plus masks ----------------
__global__ void __launch_bounds__(256) k_final(const float* __restrict__ embed,
                                               const float* __restrict__ W2,
                                               const float* __restrict__ b2,
                                               float* __restrict__ out,
                                               int out_size) {
    int base = blockIdx.x * 32;
    int tid = threadIdx.x, w = tid >> 5, l = tid & 31;
    __shared__ float Ssm[32 * HID];
    for (int idx = tid; idx < 32 * HID; idx += 256)
        Ssm[idx] = g_S[(size_t)(base + (idx >> 8)) * HID + (idx & 255)];
    __syncthreads();

    float4 y0[4], y1[4];
    #pragma unroll
    for (int rr = 0; rr < 4; rr++) {
        y0[rr] = make_float4(0, 0, 0, 0);
        y1[rr] = make_float4(0, 0, 0, 0);
    }
    #pragma unroll 4
    for (int k = 0; k < HID; k++) {
        const float4* w2row = (const float4*)(W2 + k * HID);
        float4 wa = w2row[l], wb = w2row[32 + l];
        #pragma unroll
        for (int rr = 0; rr < 4; rr++) {
            float sv = Ssm[(4 * w + rr) * HID + k];
            y0[rr].x += sv * wa.x; y0[rr].y += sv * wa.y;
            y0[rr].z += sv * wa.z; y0[rr].w += sv * wa.w;
            y1[rr].x += sv * wb.x; y1[rr].y += sv * wb.y;
            y1[rr].z += sv * wb.z; y1[rr].w += sv * wb.w;
        }
    }
    const float4* b24 = (const float4*)b2;
    float4 ba = b24[l], bb = b24[32 + l];
    #pragma unroll
    for (int rr = 0; rr < 4; rr++) {
        int n = base + 4 * w + rr;
        int valid = g_valid[n];
        float cnt = (float)g_cnt[n];
        const float4* e4 = (const float4*)(embed + (size_t)g_z[n] * HID);
        float4 ea = e4[l], eb = e4[32 + l];
        float4 oa = make_float4(0, 0, 0, 0), ob = make_float4(0, 0, 0, 0);
        if (valid) {
            oa = make_float4(ea.x + y0[rr].x + cnt * ba.x,
                             ea.y + y0[rr].y + cnt * ba.y,
                             ea.z + y0[rr].z + cnt * ba.z,
                             ea.w + y0[rr].w + cnt * ba.w);
            ob = make_float4(eb.x + y1[rr].x + cnt * bb.x,
                             eb.y + y1[rr].y + cnt * bb.y,
                             eb.z + y1[rr].z + cnt * bb.z,
                             eb.w + y1[rr].w + cnt * bb.w);
        }
        ((float4*)(out + (size_t)n * HID))[l]      = oa;
        ((float4*)(out + (size_t)n * HID))[32 + l] = ob;
    }
    if (tid < 32 && out_size >= N_TOT * HID + 2 * N_TOT) {
        int n = base + tid;
        out[N_TOT * HID + n] = (n >= N_ATOMS && g_valid[n]) ? 1.0f : 0.0f;
        out[N_TOT * HID + N_TOT + n] = (n < N_ATOMS) ? 1.0f : 0.0f;
    }
}

// ---------------- launcher ----------------
extern "C" void kernel_launch(void* const* d_in, const int* in_sizes, int n_in,
                              void* d_out, int out_size) {
    const float* pos   = (const float*)d_in[0];
    const int*   an    = (const int*)  d_in[1];
    const float* cell  = (const float*)d_in[2];
    const float* embed = (const float*)d_in[3];
    const float* Wrbf  = (const float*)d_in[4];
    const float* W1    = (const float*)d_in[5];
    const float* b1    = (const float*)d_in[6];
    const float* W2    = (const float*)d_in[7];
    const float* b2    = (const float*)d_in[8];
    float* out = (float*)d_out;

    k_setup<<<(N_TOT + 255) / 256, 256>>>(pos, an, cell);
    k_cellcount<<<(N_TOT + 255) / 256, 256>>>();
    k_cellbuild<<<1, NCELL3>>>();
    k_vmask<<<N_GRID, 256>>>();
    k_pre<<<NEMB + NRBF, 256>>>(embed, Wrbf, W1);
    k_topk<<<N_TOT, 256>>>();
    k_msg<<<N_TOT, 256>>>(b1);
    k_final<<<N_TOT / 32, 256>>>(embed, W2, b2, out, out_size);
}